// round 3
// baseline (speedup 1.0000x reference)
#include <cuda_runtime.h>
#include <math.h>
#include <stdint.h>

// ---------------- problem constants ----------------
constexpr int N_ATOMS = 10000;
constexpr int N_EDGES = 64000;
constexpr int N_BATCH = 128;
constexpr int H = 600;
constexpr int G = 50;
constexpr int L = 6;
constexpr float CUTOFF = 10.0f;
constexpr float LN2 = 0.69314718055994530942f;

// ---------------- scratch (device globals; no allocs allowed) ----------------
__device__ float g_rbf[N_EDGES * G];         // [E,50]
__device__ float g_C[N_EDGES];               // [E]
__device__ float g_h[N_ATOMS * H];           // [N,H]
__device__ float g_T1[(size_t)N_EDGES * H];  // [E,H]
__device__ float g_W[(size_t)N_EDGES * H];   // [E,H]
__device__ float g_Y[N_ATOMS * H];           // [N,H]
__device__ float g_agg[N_ATOMS * H];         // [N,H]
__device__ float g_x1[N_ATOMS * H];          // [N,H]
__device__ float g_pooled[N_BATCH * H];      // [B,H]
__device__ float g_cnt[N_BATCH];

// compile-time buffer picker: keeps kernel_launch free of ALL host API calls
enum BufId { BUF_RBF = 0, BUF_T1, BUF_W, BUF_H, BUF_Y, BUF_AGG, BUF_X1,
             BUF_POOLED, BUF_PARAM };

template <int B>
__device__ __forceinline__ float* buf_ptr(float* param) {
    if constexpr (B == BUF_RBF)    return g_rbf;
    else if constexpr (B == BUF_T1)     return g_T1;
    else if constexpr (B == BUF_W)      return g_W;
    else if constexpr (B == BUF_H)      return g_h;
    else if constexpr (B == BUF_Y)      return g_Y;
    else if constexpr (B == BUF_AGG)    return g_agg;
    else if constexpr (B == BUF_X1)     return g_x1;
    else if constexpr (B == BUF_POOLED) return g_pooled;
    else return param;
}

// ---------------- helpers ----------------
__device__ __forceinline__ float sspf(float x) {
    // shifted softplus: softplus(x) - ln2, numerically stable
    return fmaxf(x, 0.0f) + log1pf(expf(-fabsf(x))) - LN2;
}

// ---------------- edge geometry: rbf + cosine cutoff ----------------
__global__ void edge_geom_kernel(const float* __restrict__ pos,
                                 const int* __restrict__ ei) {
    int e = blockIdx.x * blockDim.x + threadIdx.x;
    if (e >= N_EDGES) return;
    int s = ei[e];
    int d = ei[N_EDGES + e];
    float dx = pos[s * 3 + 0] - pos[d * 3 + 0];
    float dy = pos[s * 3 + 1] - pos[d * 3 + 1];
    float dz = pos[s * 3 + 2] - pos[d * 3 + 2];
    float dist = sqrtf(dx * dx + dy * dy + dz * dz + 1e-12f);
    g_C[e] = 0.5f * (cosf(dist * (3.14159265358979323846f / CUTOFF)) + 1.0f);
    const float step = CUTOFF / (float)(G - 1);
    const float coeff = -0.5f / (step * step);
    #pragma unroll
    for (int g = 0; g < G; g++) {
        float t = dist - step * (float)g;
        g_rbf[(size_t)e * G + g] = expf(coeff * t * t);
    }
}

// ---------------- embedding gather ----------------
__global__ void embed_kernel(const int* __restrict__ z,
                             const float* __restrict__ emb) {
    int idx = blockIdx.x * blockDim.x + threadIdx.x;
    const int total = N_ATOMS * H;
    for (; idx < total; idx += gridDim.x * blockDim.x) {
        int i = idx / H;
        int c = idx - i * H;
        g_h[idx] = emb[z[i] * H + c];
    }
}

// ---------------- zero fills ----------------
__global__ void zero_agg_kernel() {
    int idx = blockIdx.x * blockDim.x + threadIdx.x;
    const int total = N_ATOMS * H;
    for (; idx < total; idx += gridDim.x * blockDim.x) g_agg[idx] = 0.0f;
}
__global__ void zero_pool_kernel() {
    int idx = blockIdx.x * blockDim.x + threadIdx.x;
    if (idx < N_BATCH * H) g_pooled[idx] = 0.0f;
    if (idx < N_BATCH) g_cnt[idx] = 0.0f;
}

// ---------------- tiled SGEMM with fused epilogues ----------------
// C = epi(A[M,K] @ B[K,N] (+ bias))
// EPI 0: + bias (bias may be null)
// EPI 1: ssp(. + bias)
// EPI 2: (. + bias) * g_C[m]
// EPI 3: . + bias + g_h[m,n]   (residual; DST is g_h, in-place add ok)
constexpr int BM = 128, BN = 128, BK = 8, TM = 8, TN = 8;

template <int ABUF, int CBUF, int EPI>
__global__ __launch_bounds__(256, 2)
void sgemm_kernel(const float* __restrict__ Bm, const float* __restrict__ bias,
                  float* out_param, int M, int Nn, int K) {
    const float* __restrict__ A = buf_ptr<ABUF>(nullptr);
    float* __restrict__ Cc = buf_ptr<CBUF>(out_param);

    __shared__ float As[BK][BM];
    __shared__ float Bs[BK][BN];
    const int bm = blockIdx.y * BM;
    const int bn = blockIdx.x * BN;
    const int tid = threadIdx.x;          // 256 threads
    const int ty = tid >> 4;              // 0..15
    const int tx = tid & 15;              // 0..15

    float acc[TM][TN];
    #pragma unroll
    for (int i = 0; i < TM; i++)
        #pragma unroll
        for (int j = 0; j < TN; j++) acc[i][j] = 0.0f;

    for (int k0 = 0; k0 < K; k0 += BK) {
        // load A tile [BM x BK] -> As[k][m] (transposed)
        #pragma unroll
        for (int i = 0; i < 4; i++) {
            int idx = tid + i * 256;      // 0..1023
            int m = idx >> 3;
            int k = idx & 7;
            int gm = bm + m, gk = k0 + k;
            As[k][m] = (gm < M && gk < K) ? A[(size_t)gm * K + gk] : 0.0f;
        }
        // load B tile [BK x BN] -> Bs[k][n]
        #pragma unroll
        for (int i = 0; i < 4; i++) {
            int idx = tid + i * 256;
            int k = idx >> 7;
            int n = idx & 127;
            int gk = k0 + k, gn = bn + n;
            Bs[k][n] = (gk < K && gn < Nn) ? Bm[(size_t)gk * Nn + gn] : 0.0f;
        }
        __syncthreads();
        #pragma unroll
        for (int k = 0; k < BK; k++) {
            float ra[TM], rb[TN];
            #pragma unroll
            for (int i = 0; i < TM; i++) ra[i] = As[k][ty * TM + i];
            #pragma unroll
            for (int j = 0; j < TN; j++) rb[j] = Bs[k][tx * TN + j];
            #pragma unroll
            for (int i = 0; i < TM; i++)
                #pragma unroll
                for (int j = 0; j < TN; j++)
                    acc[i][j] = fmaf(ra[i], rb[j], acc[i][j]);
        }
        __syncthreads();
    }

    #pragma unroll
    for (int i = 0; i < TM; i++) {
        int gm = bm + ty * TM + i;
        if (gm >= M) continue;
        float rs = (EPI == 2) ? g_C[gm] : 0.0f;
        #pragma unroll
        for (int j = 0; j < TN; j++) {
            int gn = bn + tx * TN + j;
            if (gn >= Nn) continue;
            float v = acc[i][j];
            if (bias) v += bias[gn];
            if (EPI == 1) v = sspf(v);
            if (EPI == 2) v *= rs;
            if (EPI == 3) v += g_h[(size_t)gm * H + gn];
            Cc[(size_t)gm * Nn + gn] = v;
        }
    }
}

// ---------------- CFConv scatter: agg[dst] += Y[src] * W ----------------
__global__ void scatter_kernel(const int* __restrict__ ei) {
    int idx = blockIdx.x * blockDim.x + threadIdx.x;
    const int total = N_EDGES * H;
    for (; idx < total; idx += gridDim.x * blockDim.x) {
        int e = idx / H;
        int c = idx - e * H;
        int s = __ldg(&ei[e]);
        int d = __ldg(&ei[N_EDGES + e]);
        float v = __ldg(&g_Y[(size_t)s * H + c]) * g_W[idx];
        atomicAdd(&g_agg[(size_t)d * H + c], v);
    }
}

// ---------------- pooling ----------------
__global__ void count_kernel(const int* __restrict__ batch) {
    int i = blockIdx.x * blockDim.x + threadIdx.x;
    if (i < N_ATOMS) atomicAdd(&g_cnt[batch[i]], 1.0f);
}

__global__ void pool_sum_kernel(const int* __restrict__ batch) {
    int idx = blockIdx.x * blockDim.x + threadIdx.x;
    const int total = N_ATOMS * H;
    for (; idx < total; idx += gridDim.x * blockDim.x) {
        int i = idx / H;
        int c = idx - i * H;
        atomicAdd(&g_pooled[(size_t)batch[i] * H + c], g_h[idx]);
    }
}

__global__ void pool_div_kernel() {
    int idx = blockIdx.x * blockDim.x + threadIdx.x;
    if (idx < N_BATCH * H) {
        g_pooled[idx] /= fmaxf(g_cnt[idx / H], 1.0f);
    }
}

// ---------------- host side: ONLY kernel launches, nothing else ----------------
extern "C" void kernel_launch(void* const* d_in, const int* in_sizes, int n_in,
                              void* d_out, int out_size) {
    const int*   z         = (const int*)  d_in[0];
    const float* pos       = (const float*)d_in[1];
    const int*   batch     = (const int*)  d_in[2];
    const int*   ei        = (const int*)  d_in[3];   // [2,E]
    const float* emb       = (const float*)d_in[4];   // [100,H]
    const float* mlp_w1    = (const float*)d_in[5];   // [L,G,H]
    const float* mlp_b1    = (const float*)d_in[6];   // [L,H]
    const float* mlp_w2    = (const float*)d_in[7];   // [L,H,H]
    const float* mlp_b2    = (const float*)d_in[8];   // [L,H]
    const float* lin1_w    = (const float*)d_in[9];   // [L,H,H]
    const float* lin2_w    = (const float*)d_in[10];  // [L,H,H]
    const float* lin2_b    = (const float*)d_in[11];  // [L,H]
    const float* int_lin_w = (const float*)d_in[12];  // [L,H,H]
    const float* int_lin_b = (const float*)d_in[13];  // [L,H]
    const float* pool_w    = (const float*)d_in[14];  // [H,H]
    const float* pool_b    = (const float*)d_in[15];  // [H]
    float* out = (float*)d_out;                       // [B,H]

    // 1) edge geometry
    edge_geom_kernel<<<(N_EDGES + 255) / 256, 256>>>(pos, ei);
    // 2) embedding
    embed_kernel<<<2048, 256>>>(z, emb);

    dim3 gridE((H + BN - 1) / BN, (N_EDGES + BM - 1) / BM);   // 5 x 500
    dim3 gridN((H + BN - 1) / BN, (N_ATOMS + BM - 1) / BM);   // 5 x 79
    dim3 gridB((H + BN - 1) / BN, (N_BATCH + BM - 1) / BM);   // 5 x 1

    for (int k = 0; k < L; k++) {
        const float* w1  = mlp_w1    + (size_t)k * G * H;
        const float* b1  = mlp_b1    + (size_t)k * H;
        const float* w2  = mlp_w2    + (size_t)k * H * H;
        const float* b2  = mlp_b2    + (size_t)k * H;
        const float* l1w = lin1_w    + (size_t)k * H * H;
        const float* l2w = lin2_w    + (size_t)k * H * H;
        const float* l2b = lin2_b    + (size_t)k * H;
        const float* ilw = int_lin_w + (size_t)k * H * H;
        const float* ilb = int_lin_b + (size_t)k * H;

        // T1 = ssp(rbf @ w1 + b1)            [E,H]
        sgemm_kernel<BUF_RBF, BUF_T1, 1><<<gridE, 256>>>(w1, b1, nullptr,
                                                         N_EDGES, H, G);
        // W = (T1 @ w2 + b2) * C[e]          [E,H]
        sgemm_kernel<BUF_T1, BUF_W, 2><<<gridE, 256>>>(w2, b2, nullptr,
                                                       N_EDGES, H, H);
        // Y = h @ lin1_w                     [N,H]
        sgemm_kernel<BUF_H, BUF_Y, 0><<<gridN, 256>>>(l1w, nullptr, nullptr,
                                                      N_ATOMS, H, H);
        // agg = scatter_add(Y[src] * W, dst)
        zero_agg_kernel<<<2048, 256>>>();
        scatter_kernel<<<4096, 256>>>(ei);
        // x1 = ssp(agg @ lin2_w + lin2_b)
        sgemm_kernel<BUF_AGG, BUF_X1, 1><<<gridN, 256>>>(l2w, l2b, nullptr,
                                                         N_ATOMS, H, H);
        // h = h + (x1 @ int_lin_w + int_lin_b)
        sgemm_kernel<BUF_X1, BUF_H, 3><<<gridN, 256>>>(ilw, ilb, nullptr,
                                                       N_ATOMS, H, H);
    }

    // pooling: per-graph mean
    zero_pool_kernel<<<(N_BATCH * H + 255) / 256, 256>>>();
    count_kernel<<<(N_ATOMS + 255) / 256, 256>>>(batch);
    pool_sum_kernel<<<2048, 256>>>(batch);
    pool_div_kernel<<<(N_BATCH * H + 255) / 256, 256>>>();

    // out = pooled @ pool_w + pool_b
    sgemm_kernel<BUF_POOLED, BUF_PARAM, 0><<<gridB, 256>>>(pool_w, pool_b, out,
                                                           N_BATCH, H, H);
}

// round 4
// speedup vs baseline: 2.0841x; 2.0841x over previous
#include <cuda_runtime.h>
#include <cuda_bf16.h>
#include <math.h>
#include <stdint.h>

// ---------------- problem constants ----------------
constexpr int N_ATOMS = 10000;
constexpr int N_EDGES = 64000;
constexpr int N_BATCH = 128;
constexpr int H = 600;
constexpr int G = 50;
constexpr int L = 6;
constexpr float CUTOFF = 10.0f;
constexpr float LN2 = 0.69314718055994530942f;

constexpr int KP  = 1824;   // padded 3*H (multiple of 32)
constexpr int KPG = 160;    // padded 3*G (multiple of 32)

// ---------------- scratch (device globals, zero-initialized) ----------------
__device__ __nv_bfloat16 g_rbf_s[(size_t)N_EDGES * KPG];   // [E,160] split rbf
__device__ float         g_C[N_EDGES];
__device__ float         g_h[N_ATOMS * H];
__device__ __nv_bfloat16 g_hs[(size_t)N_ATOMS * KP];
__device__ __nv_bfloat16 g_T1s[(size_t)N_EDGES * KP];      // 233 MB
__device__ float         g_W[(size_t)N_EDGES * H];         // 153 MB
__device__ float         g_Y[N_ATOMS * H];
__device__ float         g_agg[N_ATOMS * H];
__device__ __nv_bfloat16 g_aggs[(size_t)N_ATOMS * KP];
__device__ __nv_bfloat16 g_x1s[(size_t)N_ATOMS * KP];
__device__ float         g_pooled[N_BATCH * H];
__device__ __nv_bfloat16 g_pooled_s[(size_t)N_BATCH * KP];
__device__ float         g_cnt[N_BATCH];
// split weights (refreshed every launch; pad rows stay zero)
__device__ __nv_bfloat16 g_w1s[(size_t)KPG * H];
__device__ __nv_bfloat16 g_w2s[(size_t)KP * H];
__device__ __nv_bfloat16 g_l1ws[(size_t)KP * H];
__device__ __nv_bfloat16 g_l2ws[(size_t)KP * H];
__device__ __nv_bfloat16 g_ilws[(size_t)KP * H];
__device__ __nv_bfloat16 g_pws[(size_t)KP * H];

// ---------------- compile-time buffer picker ----------------
enum BufId { B_NONE = -1,
             B_RBFS = 0, B_T1S, B_HS, B_AGGS, B_X1S, B_POOLS,
             B_W1S, B_W2S, B_L1WS, B_L2WS, B_ILWS, B_PWS,
             B_W, B_Y, B_H, B_AGG, B_POOLED, B_PARAM };

template <int B>
__device__ __forceinline__ __nv_bfloat16* bbuf() {
    if constexpr (B == B_RBFS)  return g_rbf_s;
    else if constexpr (B == B_T1S)   return g_T1s;
    else if constexpr (B == B_HS)    return g_hs;
    else if constexpr (B == B_AGGS)  return g_aggs;
    else if constexpr (B == B_X1S)   return g_x1s;
    else if constexpr (B == B_POOLS) return g_pooled_s;
    else if constexpr (B == B_W1S)   return g_w1s;
    else if constexpr (B == B_W2S)   return g_w2s;
    else if constexpr (B == B_L1WS)  return g_l1ws;
    else if constexpr (B == B_L2WS)  return g_l2ws;
    else if constexpr (B == B_ILWS)  return g_ilws;
    else return g_pws;
}
template <int B>
__device__ __forceinline__ float* fbuf(float* p) {
    if constexpr (B == B_W)      return g_W;
    else if constexpr (B == B_Y)      return g_Y;
    else if constexpr (B == B_H)      return g_h;
    else if constexpr (B == B_AGG)    return g_agg;
    else if constexpr (B == B_POOLED) return g_pooled;
    else return p;
}

// ---------------- helpers ----------------
__device__ __forceinline__ float sspf(float x) {
    return fmaxf(x, 0.0f) + log1pf(expf(-fabsf(x))) - LN2;
}
__device__ __forceinline__ void split2(float v, __nv_bfloat16& hi, __nv_bfloat16& lo) {
    hi = __float2bfloat16(v);
    lo = __float2bfloat16(v - __bfloat162float(hi));
}

// ---------------- edge geometry: split rbf + cosine cutoff ----------------
__global__ void edge_geom_kernel(const float* __restrict__ pos,
                                 const int* __restrict__ ei) {
    int e = blockIdx.x * blockDim.x + threadIdx.x;
    if (e >= N_EDGES) return;
    int s = ei[e];
    int d = ei[N_EDGES + e];
    float dx = pos[s * 3 + 0] - pos[d * 3 + 0];
    float dy = pos[s * 3 + 1] - pos[d * 3 + 1];
    float dz = pos[s * 3 + 2] - pos[d * 3 + 2];
    float dist = sqrtf(dx * dx + dy * dy + dz * dz + 1e-12f);
    g_C[e] = 0.5f * (cosf(dist * (3.14159265358979323846f / CUTOFF)) + 1.0f);
    const float step = CUTOFF / (float)(G - 1);
    const float coeff = -0.5f / (step * step);
    #pragma unroll
    for (int g = 0; g < G; g++) {
        float t = dist - step * (float)g;
        float v = expf(coeff * t * t);
        __nv_bfloat16 hi, lo; split2(v, hi, lo);
        size_t base = (size_t)e * KPG;
        g_rbf_s[base + g]          = hi;
        g_rbf_s[base + G + g]      = lo;
        g_rbf_s[base + 2 * G + g]  = hi;
    }
}

// ---------------- embedding gather (fp32 + split) ----------------
__global__ void embed_kernel(const int* __restrict__ z,
                             const float* __restrict__ emb) {
    int idx = blockIdx.x * blockDim.x + threadIdx.x;
    const int total = N_ATOMS * H;
    for (; idx < total; idx += gridDim.x * blockDim.x) {
        int i = idx / H;
        int c = idx - i * H;
        float v = emb[z[i] * H + c];
        g_h[idx] = v;
        __nv_bfloat16 hi, lo; split2(v, hi, lo);
        size_t base = (size_t)i * KP;
        g_hs[base + c]         = hi;
        g_hs[base + H + c]     = lo;
        g_hs[base + 2 * H + c] = hi;
    }
}

// ---------------- weight split: W[K,600] fp32 -> [hi;hi;lo] bf16 ----------------
template <int DSTB>
__global__ void split_w_kernel(const float* __restrict__ src, int K) {
    __nv_bfloat16* dst = bbuf<DSTB>();
    int idx = blockIdx.x * blockDim.x + threadIdx.x;
    int total = K * H;
    if (idx >= total) return;
    int r = idx / H, n = idx - r * H;
    __nv_bfloat16 hi, lo; split2(src[idx], hi, lo);
    dst[(size_t)r * H + n]           = hi;
    dst[(size_t)(K + r) * H + n]     = hi;
    dst[(size_t)(2 * K + r) * H + n] = lo;
}

// ---------------- activation split: X[M,600] fp32 -> [hi|lo|hi] ----------------
template <int SRCF, int DSTB>
__global__ void split_act_kernel(int M) {
    const float* src = fbuf<SRCF>(nullptr);
    __nv_bfloat16* dst = bbuf<DSTB>();
    int idx = blockIdx.x * blockDim.x + threadIdx.x;
    int total = M * H;
    if (idx >= total) return;
    int m = idx / H, k = idx - m * H;
    __nv_bfloat16 hi, lo; split2(src[idx], hi, lo);
    size_t base = (size_t)m * KP;
    dst[base + k]         = hi;
    dst[base + H + k]     = lo;
    dst[base + 2 * H + k] = hi;
}

// ---------------- zero fills ----------------
__global__ void zero_agg_kernel() {
    int idx = blockIdx.x * blockDim.x + threadIdx.x;
    const int total = N_ATOMS * H;
    for (; idx < total; idx += gridDim.x * blockDim.x) g_agg[idx] = 0.0f;
}
__global__ void zero_pool_kernel() {
    int idx = blockIdx.x * blockDim.x + threadIdx.x;
    if (idx < N_BATCH * H) g_pooled[idx] = 0.0f;
    if (idx < N_BATCH) g_cnt[idx] = 0.0f;
}

// ---------------- HMMA GEMM: C = epi(A_split @ B_split + bias) ----------------
// A: [M, KPa] bf16 row-major (split layout). B: [KPa, 600] bf16 row-major.
// Block 128x128x32, 8 warps (4m x 2n), warp tile 32x64, mma m16n8k16.
// EPI: 0 = +bias, 1 = ssp(+bias), 2 = (+bias)*g_C[m], 3 = +bias + g_h[m,n]
constexpr int GBM = 128, GBN = 128, GBK = 32;
constexpr int APAD = 8, BPAD = 8;

#define MMA16816(ac, A0, A1, A2, A3, B0, B1)                              \
    asm volatile(                                                         \
        "mma.sync.aligned.m16n8k16.row.col.f32.bf16.bf16.f32 "            \
        "{%0,%1,%2,%3},{%4,%5,%6,%7},{%8,%9},{%0,%1,%2,%3};\n"            \
        : "+f"(ac[0]), "+f"(ac[1]), "+f"(ac[2]), "+f"(ac[3])              \
        : "r"(A0), "r"(A1), "r"(A2), "r"(A3), "r"(B0), "r"(B1))

template <int ABUF, int BBUF, int CF32, int CSPL, int EPI>
__global__ __launch_bounds__(256)
void hgemm_kernel(const float* __restrict__ bias, float* out_param,
                  int M, int KPa) {
    const __nv_bfloat16* __restrict__ A  = bbuf<ABUF>();
    const __nv_bfloat16* __restrict__ Bw = bbuf<BBUF>();
    float* Cf = nullptr;
    if constexpr (CF32 != B_NONE) Cf = fbuf<CF32>(out_param);
    __nv_bfloat16* Cs = nullptr;
    if constexpr (CSPL != B_NONE) Cs = bbuf<CSPL>();

    __shared__ alignas(16) __nv_bfloat16 As[2][GBM][GBK + APAD];
    __shared__ alignas(16) __nv_bfloat16 Bs[2][GBK][GBN + BPAD];

    const int tid = threadIdx.x;
    const int lane = tid & 31, wid = tid >> 5;
    const int wm = (wid >> 1) * 32;   // warp m-offset (4 warps along m)
    const int wn = (wid & 1) * 64;    // warp n-offset (2 warps along n)
    const int bm = blockIdx.y * GBM, bn = blockIdx.x * GBN;

    float acc[2][8][4];
    #pragma unroll
    for (int mi = 0; mi < 2; mi++)
        #pragma unroll
        for (int ni = 0; ni < 8; ni++)
            #pragma unroll
            for (int c = 0; c < 4; c++) acc[mi][ni][c] = 0.0f;

    const int KT = KPa / GBK;

    // --- async tile loader ---
    auto load_tiles = [&](int kt, int buf) {
        int k0 = kt * GBK;
        #pragma unroll
        for (int c0 = 0; c0 < 2; c0++) {          // A: 512 x 16B chunks
            int c = tid + c0 * 256;
            int m = c >> 2, kc = (c & 3) * 8;
            const __nv_bfloat16* src = A + (size_t)(bm + m) * KPa + k0 + kc;
            uint32_t dst = (uint32_t)__cvta_generic_to_shared(&As[buf][m][kc]);
            int sz = (bm + m < M) ? 16 : 0;
            asm volatile("cp.async.cg.shared.global [%0],[%1],16,%2;\n"
                         :: "r"(dst), "l"(src), "r"(sz));
        }
        #pragma unroll
        for (int c0 = 0; c0 < 2; c0++) {          // B: 512 x 16B chunks
            int c = tid + c0 * 256;
            int k = c >> 4, nc = (c & 15) * 8;
            const __nv_bfloat16* src = Bw + (size_t)(k0 + k) * H + bn + nc;
            uint32_t dst = (uint32_t)__cvta_generic_to_shared(&Bs[buf][k][nc]);
            int sz = (bn + nc < H) ? 16 : 0;
            asm volatile("cp.async.cg.shared.global [%0],[%1],16,%2;\n"
                         :: "r"(dst), "l"(src), "r"(sz));
        }
        asm volatile("cp.async.commit_group;\n");
    };

    load_tiles(0, 0);
    for (int kt = 0; kt < KT; kt++) {
        int buf = kt & 1;
        if (kt + 1 < KT) {
            load_tiles(kt + 1, buf ^ 1);
            asm volatile("cp.async.wait_group 1;\n");
        } else {
            asm volatile("cp.async.wait_group 0;\n");
        }
        __syncthreads();

        #pragma unroll
        for (int ks = 0; ks < 2; ks++) {
            const int kk = ks * 16;
            uint32_t a[2][4], b[4][4];
            #pragma unroll
            for (int mi = 0; mi < 2; mi++) {
                int row = wm + mi * 16 + (lane & 15);
                int col = kk + (lane >> 4) * 8;
                uint32_t addr = (uint32_t)__cvta_generic_to_shared(&As[buf][row][col]);
                asm volatile("ldmatrix.sync.aligned.m8n8.x4.shared.b16 {%0,%1,%2,%3},[%4];\n"
                             : "=r"(a[mi][0]), "=r"(a[mi][1]), "=r"(a[mi][2]), "=r"(a[mi][3])
                             : "r"(addr));
            }
            #pragma unroll
            for (int ng = 0; ng < 4; ng++) {
                int row = kk + (lane & 15);
                int col = wn + ng * 16 + (lane >> 4) * 8;
                uint32_t addr = (uint32_t)__cvta_generic_to_shared(&Bs[buf][row][col]);
                asm volatile("ldmatrix.sync.aligned.m8n8.x4.trans.shared.b16 {%0,%1,%2,%3},[%4];\n"
                             : "=r"(b[ng][0]), "=r"(b[ng][1]), "=r"(b[ng][2]), "=r"(b[ng][3])
                             : "r"(addr));
            }
            #pragma unroll
            for (int mi = 0; mi < 2; mi++)
                #pragma unroll
                for (int ni = 0; ni < 8; ni++) {
                    uint32_t b0 = b[ni >> 1][(ni & 1) * 2 + 0];
                    uint32_t b1 = b[ni >> 1][(ni & 1) * 2 + 1];
                    MMA16816(acc[mi][ni], a[mi][0], a[mi][1], a[mi][2], a[mi][3], b0, b1);
                }
        }
        __syncthreads();
    }

    // --- epilogue ---
    #pragma unroll
    for (int mi = 0; mi < 2; mi++) {
        #pragma unroll
        for (int r = 0; r < 2; r++) {
            int gm = bm + wm + mi * 16 + (lane >> 2) + r * 8;
            if (gm >= M) continue;
            float cs = 0.0f;
            if constexpr (EPI == 2) cs = g_C[gm];
            #pragma unroll
            for (int ni = 0; ni < 8; ni++) {
                #pragma unroll
                for (int cc = 0; cc < 2; cc++) {
                    int gn = bn + wn + ni * 8 + (lane & 3) * 2 + cc;
                    if (gn >= H) continue;
                    float v = acc[mi][ni][r * 2 + cc];
                    if (bias) v += bias[gn];
                    if constexpr (EPI == 1) v = sspf(v);
                    if constexpr (EPI == 2) v *= cs;
                    if constexpr (EPI == 3) v += g_h[(size_t)gm * H + gn];
                    if constexpr (CF32 != B_NONE) Cf[(size_t)gm * H + gn] = v;
                    if constexpr (CSPL != B_NONE) {
                        __nv_bfloat16 hi, lo; split2(v, hi, lo);
                        size_t base = (size_t)gm * KP;
                        Cs[base + gn]         = hi;
                        Cs[base + H + gn]     = lo;
                        Cs[base + 2 * H + gn] = hi;
                    }
                }
            }
        }
    }
}

// ---------------- CFConv scatter: agg[dst] += Y[src] * W ----------------
__global__ void scatter_kernel(const int* __restrict__ ei) {
    int idx = blockIdx.x * blockDim.x + threadIdx.x;
    const int total = N_EDGES * H;
    for (; idx < total; idx += gridDim.x * blockDim.x) {
        int e = idx / H;
        int c = idx - e * H;
        int s = __ldg(&ei[e]);
        int d = __ldg(&ei[N_EDGES + e]);
        float v = __ldg(&g_Y[(size_t)s * H + c]) * g_W[idx];
        atomicAdd(&g_agg[(size_t)d * H + c], v);
    }
}

// ---------------- pooling ----------------
__global__ void count_kernel(const int* __restrict__ batch) {
    int i = blockIdx.x * blockDim.x + threadIdx.x;
    if (i < N_ATOMS) atomicAdd(&g_cnt[batch[i]], 1.0f);
}
__global__ void pool_sum_kernel(const int* __restrict__ batch) {
    int idx = blockIdx.x * blockDim.x + threadIdx.x;
    const int total = N_ATOMS * H;
    for (; idx < total; idx += gridDim.x * blockDim.x) {
        int i = idx / H;
        int c = idx - i * H;
        atomicAdd(&g_pooled[(size_t)batch[i] * H + c], g_h[idx]);
    }
}
__global__ void pool_div_kernel() {
    int idx = blockIdx.x * blockDim.x + threadIdx.x;
    if (idx < N_BATCH * H) g_pooled[idx] /= fmaxf(g_cnt[idx / H], 1.0f);
}

// ---------------- host side: only kernel launches ----------------
extern "C" void kernel_launch(void* const* d_in, const int* in_sizes, int n_in,
                              void* d_out, int out_size) {
    const int*   z         = (const int*)  d_in[0];
    const float* pos       = (const float*)d_in[1];
    const int*   batch     = (const int*)  d_in[2];
    const int*   ei        = (const int*)  d_in[3];
    const float* emb       = (const float*)d_in[4];
    const float* mlp_w1    = (const float*)d_in[5];
    const float* mlp_b1    = (const float*)d_in[6];
    const float* mlp_w2    = (const float*)d_in[7];
    const float* mlp_b2    = (const float*)d_in[8];
    const float* lin1_w    = (const float*)d_in[9];
    const float* lin2_w    = (const float*)d_in[10];
    const float* lin2_b    = (const float*)d_in[11];
    const float* int_lin_w = (const float*)d_in[12];
    const float* int_lin_b = (const float*)d_in[13];
    const float* pool_w    = (const float*)d_in[14];
    const float* pool_b    = (const float*)d_in[15];
    float* out = (float*)d_out;

    edge_geom_kernel<<<(N_EDGES + 255) / 256, 256>>>(pos, ei);
    embed_kernel<<<2048, 256>>>(z, emb);

    const dim3 gridE(5, (N_EDGES + GBM - 1) / GBM);   // 5 x 500
    const dim3 gridN(5, (N_ATOMS + GBM - 1) / GBM);   // 5 x 79
    const dim3 gridB(5, 1);
    const int SW_BLK = (H * H + 255) / 256;
    const int SW_BLK1 = (G * H + 255) / 256;
    const int SA_BLK = (N_ATOMS * H + 255) / 256;

    for (int k = 0; k < L; k++) {
        const float* w1  = mlp_w1    + (size_t)k * G * H;
        const float* b1  = mlp_b1    + (size_t)k * H;
        const float* w2  = mlp_w2    + (size_t)k * H * H;
        const float* b2  = mlp_b2    + (size_t)k * H;
        const float* l1w = lin1_w    + (size_t)k * H * H;
        const float* l2w = lin2_w    + (size_t)k * H * H;
        const float* l2b = lin2_b    + (size_t)k * H;
        const float* ilw = int_lin_w + (size_t)k * H * H;
        const float* ilb = int_lin_b + (size_t)k * H;

        split_w_kernel<B_W1S><<<SW_BLK1, 256>>>(w1, G);
        split_w_kernel<B_W2S><<<SW_BLK, 256>>>(w2, H);
        split_w_kernel<B_L1WS><<<SW_BLK, 256>>>(l1w, H);
        split_w_kernel<B_L2WS><<<SW_BLK, 256>>>(l2w, H);
        split_w_kernel<B_ILWS><<<SW_BLK, 256>>>(ilw, H);

        // T1s = split(ssp(rbf @ w1 + b1))
        hgemm_kernel<B_RBFS, B_W1S, B_NONE, B_T1S, 1>
            <<<gridE, 256>>>(b1, nullptr, N_EDGES, KPG);
        // W = (T1 @ w2 + b2) * C
        hgemm_kernel<B_T1S, B_W2S, B_W, B_NONE, 2>
            <<<gridE, 256>>>(b2, nullptr, N_EDGES, KP);
        // Y = h @ lin1_w
        hgemm_kernel<B_HS, B_L1WS, B_Y, B_NONE, 0>
            <<<gridN, 256>>>(nullptr, nullptr, N_ATOMS, KP);
        // agg = scatter_add(Y[src] * W, dst)
        zero_agg_kernel<<<2048, 256>>>();
        scatter_kernel<<<4096, 256>>>(ei);
        split_act_kernel<B_AGG, B_AGGS><<<SA_BLK, 256>>>(N_ATOMS);
        // x1s = split(ssp(agg @ lin2_w + lin2_b))
        hgemm_kernel<B_AGGS, B_L2WS, B_NONE, B_X1S, 1>
            <<<gridN, 256>>>(l2b, nullptr, N_ATOMS, KP);
        // h = h + (x1 @ int_lin_w + int_lin_b); also refresh hs
        hgemm_kernel<B_X1S, B_ILWS, B_H, B_HS, 3>
            <<<gridN, 256>>>(ilb, nullptr, N_ATOMS, KP);
    }

    zero_pool_kernel<<<(N_BATCH * H + 255) / 256, 256>>>();
    count_kernel<<<(N_ATOMS + 255) / 256, 256>>>(batch);
    pool_sum_kernel<<<2048, 256>>>(batch);
    pool_div_kernel<<<(N_BATCH * H + 255) / 256, 256>>>();
    split_act_kernel<B_POOLED, B_POOLS><<<(N_BATCH * H + 255) / 256, 256>>>(N_BATCH);
    split_w_kernel<B_PWS><<<SW_BLK, 256>>>(pool_w, H);
    hgemm_kernel<B_POOLS, B_PWS, B_PARAM, B_NONE, 0>
        <<<gridB, 256>>>(pool_b, out, N_BATCH, KP);
}

// round 7
// speedup vs baseline: 3.8095x; 1.8279x over previous
#include <cuda_runtime.h>
#include <cuda_bf16.h>
#include <math.h>
#include <stdint.h>

// ---------------- problem constants ----------------
constexpr int N_ATOMS = 10000;
constexpr int N_EDGES = 64000;
constexpr int N_BATCH = 128;
constexpr int H = 600;
constexpr int G = 50;
constexpr int L = 6;
constexpr float CUTOFF = 10.0f;
constexpr float LN2 = 0.69314718055994530942f;

constexpr int KP  = 1824;   // padded 3*H (multiple of 32)
constexpr int KPG = 160;    // padded 3*G (multiple of 32)
constexpr int S_TAB = 8192; // distance table rows
constexpr float DMAX = 8.66035f; // sqrt(3)*5 + margin

// ---------------- scratch (device globals, zero-initialized) ----------------
__device__ __nv_bfloat16 g_rbf_s[(size_t)S_TAB * KPG];    // split rbf TABLE
__device__ float         g_Ct[S_TAB];                     // cutoff at table pts
__device__ int           g_ei0[N_EDGES];                  // lerp base index
__device__ float         g_ef[N_EDGES];                   // lerp fraction
__device__ float         g_h[N_ATOMS * H];
__device__ __nv_bfloat16 g_hs[(size_t)N_ATOMS * KP];
__device__ __nv_bfloat16 g_T1s[(size_t)S_TAB * KP];       // split T1 TABLE
__device__ float         g_Wtab[(size_t)S_TAB * H];       // fp32 W TABLE
__device__ float         g_Y[N_ATOMS * H];
__device__ float         g_agg[N_ATOMS * H];
__device__ __nv_bfloat16 g_aggs[(size_t)N_ATOMS * KP];
__device__ __nv_bfloat16 g_x1s[(size_t)N_ATOMS * KP];
__device__ float         g_pooled[N_BATCH * H];
__device__ __nv_bfloat16 g_pooled_s[(size_t)N_BATCH * KP];
__device__ float         g_cnt[N_BATCH];
// split weights (refreshed every launch; pad rows stay zero)
__device__ __nv_bfloat16 g_w1s[(size_t)KPG * H];
__device__ __nv_bfloat16 g_w2s[(size_t)KP * H];
__device__ __nv_bfloat16 g_l1ws[(size_t)KP * H];
__device__ __nv_bfloat16 g_l2ws[(size_t)KP * H];
__device__ __nv_bfloat16 g_ilws[(size_t)KP * H];
__device__ __nv_bfloat16 g_pws[(size_t)KP * H];

// ---------------- compile-time buffer picker ----------------
enum BufId { B_NONE = -1,
             B_RBFS = 0, B_T1S, B_HS, B_AGGS, B_X1S, B_POOLS,
             B_W1S, B_W2S, B_L1WS, B_L2WS, B_ILWS, B_PWS,
             B_WTAB, B_Y, B_H, B_AGG, B_POOLED, B_PARAM };

template <int B>
__device__ __forceinline__ __nv_bfloat16* bbuf() {
    if constexpr (B == B_RBFS)       return g_rbf_s;
    else if constexpr (B == B_T1S)   return g_T1s;
    else if constexpr (B == B_HS)    return g_hs;
    else if constexpr (B == B_AGGS)  return g_aggs;
    else if constexpr (B == B_X1S)   return g_x1s;
    else if constexpr (B == B_POOLS) return g_pooled_s;
    else if constexpr (B == B_W1S)   return g_w1s;
    else if constexpr (B == B_W2S)   return g_w2s;
    else if constexpr (B == B_L1WS)  return g_l1ws;
    else if constexpr (B == B_L2WS)  return g_l2ws;
    else if constexpr (B == B_ILWS)  return g_ilws;
    else return g_pws;
}
template <int B>
__device__ __forceinline__ float* fbuf(float* p) {
    if constexpr (B == B_WTAB)        return g_Wtab;
    else if constexpr (B == B_Y)      return g_Y;
    else if constexpr (B == B_H)      return g_h;
    else if constexpr (B == B_AGG)    return g_agg;
    else if constexpr (B == B_POOLED) return g_pooled;
    else return p;
}

// ---------------- helpers ----------------
__device__ __forceinline__ float sspf(float x) {
    return fmaxf(x, 0.0f) + log1pf(expf(-fabsf(x))) - LN2;
}
__device__ __forceinline__ void split2(float v, __nv_bfloat16& hi, __nv_bfloat16& lo) {
    hi = __float2bfloat16(v);
    lo = __float2bfloat16(v - __bfloat162float(hi));
}

// ---------------- edge geometry: per-edge lerp coords only ----------------
__global__ void edge_geom_kernel(const float* __restrict__ pos,
                                 const int* __restrict__ ei) {
    int e = blockIdx.x * blockDim.x + threadIdx.x;
    if (e >= N_EDGES) return;
    int s = ei[e];
    int d = ei[N_EDGES + e];
    float dx = pos[s * 3 + 0] - pos[d * 3 + 0];
    float dy = pos[s * 3 + 1] - pos[d * 3 + 1];
    float dz = pos[s * 3 + 2] - pos[d * 3 + 2];
    float dist = sqrtf(dx * dx + dy * dy + dz * dz + 1e-12f);
    float x = dist * ((float)(S_TAB - 1) / DMAX);
    int i0 = (int)x;
    if (i0 > S_TAB - 2) i0 = S_TAB - 2;
    g_ei0[e] = i0;
    g_ef[e] = x - (float)i0;
}

// ---------------- rbf table (once per launch): split rbf at table points ----
__global__ void rbf_table_kernel() {
    int i = blockIdx.x * blockDim.x + threadIdx.x;
    if (i >= S_TAB) return;
    float dist = (float)i * (DMAX / (float)(S_TAB - 1));
    g_Ct[i] = 0.5f * (cosf(dist * (3.14159265358979323846f / CUTOFF)) + 1.0f);
    const float step = CUTOFF / (float)(G - 1);
    const float coeff = -0.5f / (step * step);
    size_t base = (size_t)i * KPG;
    #pragma unroll
    for (int g = 0; g < G; g++) {
        float t = dist - step * (float)g;
        float v = expf(coeff * t * t);
        __nv_bfloat16 hi, lo; split2(v, hi, lo);
        g_rbf_s[base + g]         = hi;
        g_rbf_s[base + G + g]     = lo;
        g_rbf_s[base + 2 * G + g] = hi;
    }
}

// ---------------- embedding gather (fp32 + split) ----------------
__global__ void embed_kernel(const int* __restrict__ z,
                             const float* __restrict__ emb) {
    int idx = blockIdx.x * blockDim.x + threadIdx.x;
    const int total = N_ATOMS * H;
    for (; idx < total; idx += gridDim.x * blockDim.x) {
        int i = idx / H;
        int c = idx - i * H;
        float v = emb[z[i] * H + c];
        g_h[idx] = v;
        __nv_bfloat16 hi, lo; split2(v, hi, lo);
        size_t base = (size_t)i * KP;
        g_hs[base + c]         = hi;
        g_hs[base + H + c]     = lo;
        g_hs[base + 2 * H + c] = hi;
    }
}

// ---------------- weight split: W[K,600] fp32 -> [hi;hi;lo] bf16 ----------------
template <int DSTB>
__global__ void split_w_kernel(const float* __restrict__ src, int K) {
    __nv_bfloat16* dst = bbuf<DSTB>();
    int idx = blockIdx.x * blockDim.x + threadIdx.x;
    int total = K * H;
    if (idx >= total) return;
    int r = idx / H, n = idx - r * H;
    __nv_bfloat16 hi, lo; split2(src[idx], hi, lo);
    dst[(size_t)r * H + n]           = hi;
    dst[(size_t)(K + r) * H + n]     = hi;
    dst[(size_t)(2 * K + r) * H + n] = lo;
}

// ---------------- activation split: X[M,600] fp32 -> [hi|lo|hi] ----------------
template <int SRCF, int DSTB>
__global__ void split_act_kernel(int M) {
    const float* src = fbuf<SRCF>(nullptr);
    __nv_bfloat16* dst = bbuf<DSTB>();
    int idx = blockIdx.x * blockDim.x + threadIdx.x;
    int total = M * H;
    if (idx >= total) return;
    int m = idx / H, k = idx - m * H;
    __nv_bfloat16 hi, lo; split2(src[idx], hi, lo);
    size_t base = (size_t)m * KP;
    dst[base + k]         = hi;
    dst[base + H + k]     = lo;
    dst[base + 2 * H + k] = hi;
}

// ---------------- zero fills ----------------
__global__ void zero_agg_kernel() {
    int idx = blockIdx.x * blockDim.x + threadIdx.x;
    const int total = N_ATOMS * H;
    for (; idx < total; idx += gridDim.x * blockDim.x) g_agg[idx] = 0.0f;
}
__global__ void zero_pool_kernel() {
    int idx = blockIdx.x * blockDim.x + threadIdx.x;
    if (idx < N_BATCH * H) g_pooled[idx] = 0.0f;
    if (idx < N_BATCH) g_cnt[idx] = 0.0f;
}

// ---------------- HMMA GEMM: C = epi(A_split @ B_split + bias) ----------------
// A: [M, KPa] bf16 row-major (split layout). B: [KPa, 600] bf16 row-major.
// Block 128x128x32, 8 warps (4m x 2n), warp tile 32x64, mma m16n8k16.
// EPI: 0 = +bias, 1 = ssp(+bias), 2 = (+bias)*g_Ct[m], 3 = +bias + g_h[m,n]
constexpr int GBM = 128, GBN = 128, GBK = 32;
constexpr int APAD = 8, BPAD = 8;

#define MMA16816(ac, A0, A1, A2, A3, B0, B1)                              \
    asm volatile(                                                         \
        "mma.sync.aligned.m16n8k16.row.col.f32.bf16.bf16.f32 "            \
        "{%0,%1,%2,%3},{%4,%5,%6,%7},{%8,%9},{%0,%1,%2,%3};\n"            \
        : "+f"(ac[0]), "+f"(ac[1]), "+f"(ac[2]), "+f"(ac[3])              \
        : "r"(A0), "r"(A1), "r"(A2), "r"(A3), "r"(B0), "r"(B1))

template <int ABUF, int BBUF, int CF32, int CSPL, int EPI>
__global__ __launch_bounds__(256)
void hgemm_kernel(const float* __restrict__ bias, float* out_param,
                  int M, int KPa) {
    const __nv_bfloat16* __restrict__ A  = bbuf<ABUF>();
    const __nv_bfloat16* __restrict__ Bw = bbuf<BBUF>();
    float* Cf = nullptr;
    if constexpr (CF32 != B_NONE) Cf = fbuf<CF32>(out_param);
    __nv_bfloat16* Cs = nullptr;
    if constexpr (CSPL != B_NONE) Cs = bbuf<CSPL>();

    __shared__ alignas(16) __nv_bfloat16 As[2][GBM][GBK + APAD];
    __shared__ alignas(16) __nv_bfloat16 Bs[2][GBK][GBN + BPAD];

    const int tid = threadIdx.x;
    const int lane = tid & 31, wid = tid >> 5;
    const int wm = (wid >> 1) * 32;
    const int wn = (wid & 1) * 64;
    const int bm = blockIdx.y * GBM, bn = blockIdx.x * GBN;

    float acc[2][8][4];
    #pragma unroll
    for (int mi = 0; mi < 2; mi++)
        #pragma unroll
        for (int ni = 0; ni < 8; ni++)
            #pragma unroll
            for (int c = 0; c < 4; c++) acc[mi][ni][c] = 0.0f;

    const int KT = KPa / GBK;

    auto load_tiles = [&](int kt, int buf) {
        int k0 = kt * GBK;
        #pragma unroll
        for (int c0 = 0; c0 < 2; c0++) {
            int c = tid + c0 * 256;
            int m = c >> 2, kc = (c & 3) * 8;
            const __nv_bfloat16* src = A + (size_t)(bm + m) * KPa + k0 + kc;
            uint32_t dst = (uint32_t)__cvta_generic_to_shared(&As[buf][m][kc]);
            int sz = (bm + m < M) ? 16 : 0;
            asm volatile("cp.async.cg.shared.global [%0],[%1],16,%2;\n"
                         :: "r"(dst), "l"(src), "r"(sz));
        }
        #pragma unroll
        for (int c0 = 0; c0 < 2; c0++) {
            int c = tid + c0 * 256;
            int k = c >> 4, nc = (c & 15) * 8;
            const __nv_bfloat16* src = Bw + (size_t)(k0 + k) * H + bn + nc;
            uint32_t dst = (uint32_t)__cvta_generic_to_shared(&Bs[buf][k][nc]);
            int sz = (bn + nc < H) ? 16 : 0;
            asm volatile("cp.async.cg.shared.global [%0],[%1],16,%2;\n"
                         :: "r"(dst), "l"(src), "r"(sz));
        }
        asm volatile("cp.async.commit_group;\n");
    };

    load_tiles(0, 0);
    for (int kt = 0; kt < KT; kt++) {
        int buf = kt & 1;
        if (kt + 1 < KT) {
            load_tiles(kt + 1, buf ^ 1);
            asm volatile("cp.async.wait_group 1;\n");
        } else {
            asm volatile("cp.async.wait_group 0;\n");
        }
        __syncthreads();

        #pragma unroll
        for (int ks = 0; ks < 2; ks++) {
            const int kk = ks * 16;
            uint32_t a[2][4], b[4][4];
            #pragma unroll
            for (int mi = 0; mi < 2; mi++) {
                int row = wm + mi * 16 + (lane & 15);
                int col = kk + (lane >> 4) * 8;
                uint32_t addr = (uint32_t)__cvta_generic_to_shared(&As[buf][row][col]);
                asm volatile("ldmatrix.sync.aligned.m8n8.x4.shared.b16 {%0,%1,%2,%3},[%4];\n"
                             : "=r"(a[mi][0]), "=r"(a[mi][1]), "=r"(a[mi][2]), "=r"(a[mi][3])
                             : "r"(addr));
            }
            #pragma unroll
            for (int ng = 0; ng < 4; ng++) {
                int row = kk + (lane & 15);
                int col = wn + ng * 16 + (lane >> 4) * 8;
                uint32_t addr = (uint32_t)__cvta_generic_to_shared(&Bs[buf][row][col]);
                asm volatile("ldmatrix.sync.aligned.m8n8.x4.trans.shared.b16 {%0,%1,%2,%3},[%4];\n"
                             : "=r"(b[ng][0]), "=r"(b[ng][1]), "=r"(b[ng][2]), "=r"(b[ng][3])
                             : "r"(addr));
            }
            #pragma unroll
            for (int mi = 0; mi < 2; mi++)
                #pragma unroll
                for (int ni = 0; ni < 8; ni++) {
                    uint32_t b0 = b[ni >> 1][(ni & 1) * 2 + 0];
                    uint32_t b1 = b[ni >> 1][(ni & 1) * 2 + 1];
                    MMA16816(acc[mi][ni], a[mi][0], a[mi][1], a[mi][2], a[mi][3], b0, b1);
                }
        }
        __syncthreads();
    }

    #pragma unroll
    for (int mi = 0; mi < 2; mi++) {
        #pragma unroll
        for (int r = 0; r < 2; r++) {
            int gm = bm + wm + mi * 16 + (lane >> 2) + r * 8;
            if (gm >= M) continue;
            float cs = 0.0f;
            if constexpr (EPI == 2) cs = g_Ct[gm];
            #pragma unroll
            for (int ni = 0; ni < 8; ni++) {
                #pragma unroll
                for (int cc = 0; cc < 2; cc++) {
                    int gn = bn + wn + ni * 8 + (lane & 3) * 2 + cc;
                    if (gn >= H) continue;
                    float v = acc[mi][ni][r * 2 + cc];
                    if (bias) v += bias[gn];
                    if constexpr (EPI == 1) v = sspf(v);
                    if constexpr (EPI == 2) v *= cs;
                    if constexpr (EPI == 3) v += g_h[(size_t)gm * H + gn];
                    if constexpr (CF32 != B_NONE) Cf[(size_t)gm * H + gn] = v;
                    if constexpr (CSPL != B_NONE) {
                        __nv_bfloat16 hi, lo; split2(v, hi, lo);
                        size_t base = (size_t)gm * KP;
                        Cs[base + gn]         = hi;
                        Cs[base + H + gn]     = lo;
                        Cs[base + 2 * H + gn] = hi;
                    }
                }
            }
        }
    }
}

// ---------------- CFConv scatter with table lerp ----------------
// agg[dst] += Y[src] * lerp(Wtab[i0], Wtab[i0+1], f)
__global__ void scatter_kernel(const int* __restrict__ ei) {
    int idx = blockIdx.x * blockDim.x + threadIdx.x;
    const int total = N_EDGES * H;
    for (; idx < total; idx += gridDim.x * blockDim.x) {
        int e = idx / H;
        int c = idx - e * H;
        int s = __ldg(&ei[e]);
        int d = __ldg(&ei[N_EDGES + e]);
        int i0 = __ldg(&g_ei0[e]);
        float f = __ldg(&g_ef[e]);
        float w0 = __ldg(&g_Wtab[(size_t)i0 * H + c]);
        float w1 = __ldg(&g_Wtab[(size_t)(i0 + 1) * H + c]);
        float w = fmaf(f, w1 - w0, w0);
        float v = __ldg(&g_Y[(size_t)s * H + c]) * w;
        atomicAdd(&g_agg[(size_t)d * H + c], v);
    }
}

// ---------------- pooling ----------------
__global__ void count_kernel(const int* __restrict__ batch) {
    int i = blockIdx.x * blockDim.x + threadIdx.x;
    if (i < N_ATOMS) atomicAdd(&g_cnt[batch[i]], 1.0f);
}
__global__ void pool_sum_kernel(const int* __restrict__ batch) {
    int idx = blockIdx.x * blockDim.x + threadIdx.x;
    const int total = N_ATOMS * H;
    for (; idx < total; idx += gridDim.x * blockDim.x) {
        int i = idx / H;
        int c = idx - i * H;
        atomicAdd(&g_pooled[(size_t)batch[i] * H + c], g_h[idx]);
    }
}
__global__ void pool_div_kernel() {
    int idx = blockIdx.x * blockDim.x + threadIdx.x;
    if (idx < N_BATCH * H) g_pooled[idx] /= fmaxf(g_cnt[idx / H], 1.0f);
}

// ---------------- host side: only kernel launches ----------------
extern "C" void kernel_launch(void* const* d_in, const int* in_sizes, int n_in,
                              void* d_out, int out_size) {
    const int*   z         = (const int*)  d_in[0];
    const float* pos       = (const float*)d_in[1];
    const int*   batch     = (const int*)  d_in[2];
    const int*   ei        = (const int*)  d_in[3];
    const float* emb       = (const float*)d_in[4];
    const float* mlp_w1    = (const float*)d_in[5];
    const float* mlp_b1    = (const float*)d_in[6];
    const float* mlp_w2    = (const float*)d_in[7];
    const float* mlp_b2    = (const float*)d_in[8];
    const float* lin1_w    = (const float*)d_in[9];
    const float* lin2_w    = (const float*)d_in[10];
    const float* lin2_b    = (const float*)d_in[11];
    const float* int_lin_w = (const float*)d_in[12];
    const float* int_lin_b = (const float*)d_in[13];
    const float* pool_w    = (const float*)d_in[14];
    const float* pool_b    = (const float*)d_in[15];
    float* out = (float*)d_out;

    edge_geom_kernel<<<(N_EDGES + 255) / 256, 256>>>(pos, ei);
    rbf_table_kernel<<<(S_TAB + 255) / 256, 256>>>();
    embed_kernel<<<2048, 256>>>(z, emb);

    const dim3 gridT(5, S_TAB / GBM);                 // 5 x 64   (table GEMMs)
    const dim3 gridN(5, (N_ATOMS + GBM - 1) / GBM);   // 5 x 79
    const dim3 gridB(5, 1);
    const int SW_BLK  = (H * H + 255) / 256;
    const int SW_BLK1 = (G * H + 255) / 256;
    const int SA_BLK  = (N_ATOMS * H + 255) / 256;

    for (int k = 0; k < L; k++) {
        const float* w1  = mlp_w1    + (size_t)k * G * H;
        const float* b1  = mlp_b1    + (size_t)k * H;
        const float* w2  = mlp_w2    + (size_t)k * H * H;
        const float* b2  = mlp_b2    + (size_t)k * H;
        const float* l1w = lin1_w    + (size_t)k * H * H;
        const float* l2w = lin2_w    + (size_t)k * H * H;
        const float* l2b = lin2_b    + (size_t)k * H;
        const float* ilw = int_lin_w + (size_t)k * H * H;
        const float* ilb = int_lin_b + (size_t)k * H;

        split_w_kernel<B_W1S><<<SW_BLK1, 256>>>(w1, G);
        split_w_kernel<B_W2S><<<SW_BLK, 256>>>(w2, H);
        split_w_kernel<B_L1WS><<<SW_BLK, 256>>>(l1w, H);
        split_w_kernel<B_L2WS><<<SW_BLK, 256>>>(l2w, H);
        split_w_kernel<B_ILWS><<<SW_BLK, 256>>>(ilw, H);

        // T1 table = split(ssp(rbf_tab @ w1 + b1))        [S_TAB, H]
        hgemm_kernel<B_RBFS, B_W1S, B_NONE, B_T1S, 1>
            <<<gridT, 256>>>(b1, nullptr, S_TAB, KPG);
        // W table = (T1_tab @ w2 + b2) * C(d_tab)          [S_TAB, H] fp32
        hgemm_kernel<B_T1S, B_W2S, B_WTAB, B_NONE, 2>
            <<<gridT, 256>>>(b2, nullptr, S_TAB, KP);
        // Y = h @ lin1_w
        hgemm_kernel<B_HS, B_L1WS, B_Y, B_NONE, 0>
            <<<gridN, 256>>>(nullptr, nullptr, N_ATOMS, KP);
        // agg = scatter_add(Y[src] * lerp(Wtab, d_e), dst)
        zero_agg_kernel<<<2048, 256>>>();
        scatter_kernel<<<4096, 256>>>(ei);
        split_act_kernel<B_AGG, B_AGGS><<<SA_BLK, 256>>>(N_ATOMS);
        // x1s = split(ssp(agg @ lin2_w + lin2_b))
        hgemm_kernel<B_AGGS, B_L2WS, B_NONE, B_X1S, 1>
            <<<gridN, 256>>>(l2b, nullptr, N_ATOMS, KP);
        // h = h + (x1 @ int_lin_w + int_lin_b); also refresh hs
        hgemm_kernel<B_X1S, B_ILWS, B_H, B_HS, 3>
            <<<gridN, 256>>>(ilb, nullptr, N_ATOMS, KP);
    }

    zero_pool_kernel<<<(N_BATCH * H + 255) / 256, 256>>>();
    count_kernel<<<(N_ATOMS + 255) / 256, 256>>>(batch);
    pool_sum_kernel<<<2048, 256>>>(batch);
    pool_div_kernel<<<(N_BATCH * H + 255) / 256, 256>>>();
    split_act_kernel<B_POOLED, B_POOLS><<<(N_BATCH * H + 255) / 256, 256>>>(N_BATCH);
    split_w_kernel<B_PWS><<<SW_BLK, 256>>>(pool_w, H);
    hgemm_kernel<B_POOLS, B_PWS, B_PARAM, B_NONE, 0>
        <<<gridB, 256>>>(pool_b, out, N_BATCH, KP);
}

// round 8
// speedup vs baseline: 4.8668x; 1.2775x over previous
#include <cuda_runtime.h>
#include <cuda_bf16.h>
#include <math.h>
#include <stdint.h>

// ---------------- problem constants ----------------
constexpr int N_ATOMS = 10000;
constexpr int N_EDGES = 64000;
constexpr int N_BATCH = 128;
constexpr int H = 600;
constexpr int H4 = H / 4;          // 150 float4 per row
constexpr int G = 50;
constexpr int L = 6;
constexpr float CUTOFF = 10.0f;
constexpr float LN2 = 0.69314718055994530942f;

constexpr int KP  = 1824;   // padded 3*H (multiple of 32)
constexpr int KPG = 160;    // padded 3*G (multiple of 32)
constexpr int S_TAB = 2048; // distance table rows
constexpr float DMAX = 8.66035f; // sqrt(3)*5 + margin

// ---------------- scratch (device globals, zero-initialized) ----------------
__device__ __nv_bfloat16 g_rbf_s[(size_t)S_TAB * KPG];    // split rbf TABLE
__device__ float         g_Ct[S_TAB];                     // cutoff at table pts
__device__ int           g_ei0[N_EDGES];                  // lerp base index
__device__ float         g_ef[N_EDGES];                   // lerp fraction
__device__ float         g_h[N_ATOMS * H];
__device__ __nv_bfloat16 g_hs[(size_t)N_ATOMS * KP];
__device__ __nv_bfloat16 g_T1s[(size_t)S_TAB * KP];       // split T1 TABLE
__device__ float         g_Wtab[(size_t)S_TAB * H];       // fp32 W TABLE (4.9MB)
__device__ float         g_Y[N_ATOMS * H];
__device__ float         g_agg[N_ATOMS * H];
__device__ __nv_bfloat16 g_aggs[(size_t)N_ATOMS * KP];
__device__ __nv_bfloat16 g_x1s[(size_t)N_ATOMS * KP];
__device__ float         g_pooled[N_BATCH * H];
__device__ __nv_bfloat16 g_pooled_s[(size_t)N_BATCH * KP];
__device__ float         g_cnt[N_BATCH];
// split weights (refreshed every launch; pad rows stay zero)
__device__ __nv_bfloat16 g_w1s[(size_t)KPG * H];
__device__ __nv_bfloat16 g_w2s[(size_t)KP * H];
__device__ __nv_bfloat16 g_l1ws[(size_t)KP * H];
__device__ __nv_bfloat16 g_l2ws[(size_t)KP * H];
__device__ __nv_bfloat16 g_ilws[(size_t)KP * H];
__device__ __nv_bfloat16 g_pws[(size_t)KP * H];

// ---------------- compile-time buffer picker ----------------
enum BufId { B_NONE = -1,
             B_RBFS = 0, B_T1S, B_HS, B_AGGS, B_X1S, B_POOLS,
             B_W1S, B_W2S, B_L1WS, B_L2WS, B_ILWS, B_PWS,
             B_WTAB, B_Y, B_H, B_AGG, B_POOLED, B_PARAM };

template <int B>
__device__ __forceinline__ __nv_bfloat16* bbuf() {
    if constexpr (B == B_RBFS)       return g_rbf_s;
    else if constexpr (B == B_T1S)   return g_T1s;
    else if constexpr (B == B_HS)    return g_hs;
    else if constexpr (B == B_AGGS)  return g_aggs;
    else if constexpr (B == B_X1S)   return g_x1s;
    else if constexpr (B == B_POOLS) return g_pooled_s;
    else if constexpr (B == B_W1S)   return g_w1s;
    else if constexpr (B == B_W2S)   return g_w2s;
    else if constexpr (B == B_L1WS)  return g_l1ws;
    else if constexpr (B == B_L2WS)  return g_l2ws;
    else if constexpr (B == B_ILWS)  return g_ilws;
    else return g_pws;
}
template <int B>
__device__ __forceinline__ float* fbuf(float* p) {
    if constexpr (B == B_WTAB)        return g_Wtab;
    else if constexpr (B == B_Y)      return g_Y;
    else if constexpr (B == B_H)      return g_h;
    else if constexpr (B == B_AGG)    return g_agg;
    else if constexpr (B == B_POOLED) return g_pooled;
    else return p;
}

// ---------------- helpers ----------------
__device__ __forceinline__ float sspf(float x) {
    return fmaxf(x, 0.0f) + log1pf(expf(-fabsf(x))) - LN2;
}
__device__ __forceinline__ void split2(float v, __nv_bfloat16& hi, __nv_bfloat16& lo) {
    hi = __float2bfloat16(v);
    lo = __float2bfloat16(v - __bfloat162float(hi));
}

// ---------------- edge geometry: per-edge lerp coords only ----------------
__global__ void edge_geom_kernel(const float* __restrict__ pos,
                                 const int* __restrict__ ei) {
    int e = blockIdx.x * blockDim.x + threadIdx.x;
    if (e >= N_EDGES) return;
    int s = ei[e];
    int d = ei[N_EDGES + e];
    float dx = pos[s * 3 + 0] - pos[d * 3 + 0];
    float dy = pos[s * 3 + 1] - pos[d * 3 + 1];
    float dz = pos[s * 3 + 2] - pos[d * 3 + 2];
    float dist = sqrtf(dx * dx + dy * dy + dz * dz + 1e-12f);
    float x = dist * ((float)(S_TAB - 1) / DMAX);
    int i0 = (int)x;
    if (i0 > S_TAB - 2) i0 = S_TAB - 2;
    g_ei0[e] = i0;
    g_ef[e] = x - (float)i0;
}

// ---------------- rbf table: split rbf at table points ----------------
__global__ void rbf_table_kernel() {
    int i = blockIdx.x * blockDim.x + threadIdx.x;
    if (i >= S_TAB) return;
    float dist = (float)i * (DMAX / (float)(S_TAB - 1));
    g_Ct[i] = 0.5f * (cosf(dist * (3.14159265358979323846f / CUTOFF)) + 1.0f);
    const float step = CUTOFF / (float)(G - 1);
    const float coeff = -0.5f / (step * step);
    size_t base = (size_t)i * KPG;
    #pragma unroll
    for (int g = 0; g < G; g++) {
        float t = dist - step * (float)g;
        float v = expf(coeff * t * t);
        __nv_bfloat16 hi, lo; split2(v, hi, lo);
        g_rbf_s[base + g]         = hi;
        g_rbf_s[base + G + g]     = lo;
        g_rbf_s[base + 2 * G + g] = hi;
    }
}

// ---------------- embedding gather (fp32 + split) ----------------
__global__ void embed_kernel(const int* __restrict__ z,
                             const float* __restrict__ emb) {
    int idx = blockIdx.x * blockDim.x + threadIdx.x;
    const int total = N_ATOMS * H;
    for (; idx < total; idx += gridDim.x * blockDim.x) {
        int i = idx / H;
        int c = idx - i * H;
        float v = emb[z[i] * H + c];
        g_h[idx] = v;
        __nv_bfloat16 hi, lo; split2(v, hi, lo);
        size_t base = (size_t)i * KP;
        g_hs[base + c]         = hi;
        g_hs[base + H + c]     = lo;
        g_hs[base + 2 * H + c] = hi;
    }
}

// ---------------- weight split: W[K,600] fp32 -> [hi;hi;lo] bf16 ----------------
template <int DSTB>
__global__ void split_w_kernel(const float* __restrict__ src, int K) {
    __nv_bfloat16* dst = bbuf<DSTB>();
    int idx = blockIdx.x * blockDim.x + threadIdx.x;
    int total = K * H;
    if (idx >= total) return;
    int r = idx / H, n = idx - r * H;
    __nv_bfloat16 hi, lo; split2(src[idx], hi, lo);
    dst[(size_t)r * H + n]           = hi;
    dst[(size_t)(K + r) * H + n]     = hi;
    dst[(size_t)(2 * K + r) * H + n] = lo;
}

// combined split for the four H x H layer weights (fewer graph nodes)
__global__ void split_w4_kernel(const float* __restrict__ w2,
                                const float* __restrict__ l1w,
                                const float* __restrict__ l2w,
                                const float* __restrict__ ilw) {
    int idx = blockIdx.x * blockDim.x + threadIdx.x;
    const int per = H * H;
    if (idx >= 4 * per) return;
    int which = idx / per;
    int j = idx - which * per;
    const float* src = (which == 0) ? w2 : (which == 1) ? l1w
                     : (which == 2) ? l2w : ilw;
    __nv_bfloat16* dst = (which == 0) ? g_w2s : (which == 1) ? g_l1ws
                       : (which == 2) ? g_l2ws : g_ilws;
    int r = j / H, n = j - r * H;
    __nv_bfloat16 hi, lo; split2(src[j], hi, lo);
    dst[(size_t)r * H + n]           = hi;
    dst[(size_t)(H + r) * H + n]     = hi;
    dst[(size_t)(2 * H + r) * H + n] = lo;
}

// ---------------- activation split: X[M,600] fp32 -> [hi|lo|hi] ----------------
template <int SRCF, int DSTB>
__global__ void split_act_kernel(int M) {
    const float* src = fbuf<SRCF>(nullptr);
    __nv_bfloat16* dst = bbuf<DSTB>();
    int idx = blockIdx.x * blockDim.x + threadIdx.x;
    int total = M * H;
    if (idx >= total) return;
    int m = idx / H, k = idx - m * H;
    __nv_bfloat16 hi, lo; split2(src[idx], hi, lo);
    size_t base = (size_t)m * KP;
    dst[base + k]         = hi;
    dst[base + H + k]     = lo;
    dst[base + 2 * H + k] = hi;
}

// ---------------- zero fills (vectorized) ----------------
__global__ void zero_agg_kernel() {
    int idx = blockIdx.x * blockDim.x + threadIdx.x;
    const int total = N_ATOMS * H4;
    if (idx < total) ((float4*)g_agg)[idx] = make_float4(0.f, 0.f, 0.f, 0.f);
}
__global__ void zero_pool_kernel() {
    int idx = blockIdx.x * blockDim.x + threadIdx.x;
    if (idx < N_BATCH * H4)
        ((float4*)g_pooled)[idx] = make_float4(0.f, 0.f, 0.f, 0.f);
    if (idx < N_BATCH) g_cnt[idx] = 0.0f;
}

// ---------------- HMMA GEMM: C = epi(A_split @ B_split + bias) ----------------
constexpr int GBM = 128, GBN = 128, GBK = 32;
constexpr int APAD = 8, BPAD = 8;

#define MMA16816(ac, A0, A1, A2, A3, B0, B1)                              \
    asm volatile(                                                         \
        "mma.sync.aligned.m16n8k16.row.col.f32.bf16.bf16.f32 "            \
        "{%0,%1,%2,%3},{%4,%5,%6,%7},{%8,%9},{%0,%1,%2,%3};\n"            \
        : "+f"(ac[0]), "+f"(ac[1]), "+f"(ac[2]), "+f"(ac[3])              \
        : "r"(A0), "r"(A1), "r"(A2), "r"(A3), "r"(B0), "r"(B1))

template <int ABUF, int BBUF, int CF32, int CSPL, int EPI>
__global__ __launch_bounds__(256)
void hgemm_kernel(const float* __restrict__ bias, float* out_param,
                  int M, int KPa) {
    const __nv_bfloat16* __restrict__ A  = bbuf<ABUF>();
    const __nv_bfloat16* __restrict__ Bw = bbuf<BBUF>();
    float* Cf = nullptr;
    if constexpr (CF32 != B_NONE) Cf = fbuf<CF32>(out_param);
    __nv_bfloat16* Cs = nullptr;
    if constexpr (CSPL != B_NONE) Cs = bbuf<CSPL>();

    __shared__ alignas(16) __nv_bfloat16 As[2][GBM][GBK + APAD];
    __shared__ alignas(16) __nv_bfloat16 Bs[2][GBK][GBN + BPAD];

    const int tid = threadIdx.x;
    const int lane = tid & 31, wid = tid >> 5;
    const int wm = (wid >> 1) * 32;
    const int wn = (wid & 1) * 64;
    const int bm = blockIdx.y * GBM, bn = blockIdx.x * GBN;

    float acc[2][8][4];
    #pragma unroll
    for (int mi = 0; mi < 2; mi++)
        #pragma unroll
        for (int ni = 0; ni < 8; ni++)
            #pragma unroll
            for (int c = 0; c < 4; c++) acc[mi][ni][c] = 0.0f;

    const int KT = KPa / GBK;

    auto load_tiles = [&](int kt, int buf) {
        int k0 = kt * GBK;
        #pragma unroll
        for (int c0 = 0; c0 < 2; c0++) {
            int c = tid + c0 * 256;
            int m = c >> 2, kc = (c & 3) * 8;
            const __nv_bfloat16* src = A + (size_t)(bm + m) * KPa + k0 + kc;
            uint32_t dst = (uint32_t)__cvta_generic_to_shared(&As[buf][m][kc]);
            int sz = (bm + m < M) ? 16 : 0;
            asm volatile("cp.async.cg.shared.global [%0],[%1],16,%2;\n"
                         :: "r"(dst), "l"(src), "r"(sz));
        }
        #pragma unroll
        for (int c0 = 0; c0 < 2; c0++) {
            int c = tid + c0 * 256;
            int k = c >> 4, nc = (c & 15) * 8;
            const __nv_bfloat16* src = Bw + (size_t)(k0 + k) * H + bn + nc;
            uint32_t dst = (uint32_t)__cvta_generic_to_shared(&Bs[buf][k][nc]);
            int sz = (bn + nc < H) ? 16 : 0;
            asm volatile("cp.async.cg.shared.global [%0],[%1],16,%2;\n"
                         :: "r"(dst), "l"(src), "r"(sz));
        }
        asm volatile("cp.async.commit_group;\n");
    };

    load_tiles(0, 0);
    for (int kt = 0; kt < KT; kt++) {
        int buf = kt & 1;
        if (kt + 1 < KT) {
            load_tiles(kt + 1, buf ^ 1);
            asm volatile("cp.async.wait_group 1;\n");
        } else {
            asm volatile("cp.async.wait_group 0;\n");
        }
        __syncthreads();

        #pragma unroll
        for (int ks = 0; ks < 2; ks++) {
            const int kk = ks * 16;
            uint32_t a[2][4], b[4][4];
            #pragma unroll
            for (int mi = 0; mi < 2; mi++) {
                int row = wm + mi * 16 + (lane & 15);
                int col = kk + (lane >> 4) * 8;
                uint32_t addr = (uint32_t)__cvta_generic_to_shared(&As[buf][row][col]);
                asm volatile("ldmatrix.sync.aligned.m8n8.x4.shared.b16 {%0,%1,%2,%3},[%4];\n"
                             : "=r"(a[mi][0]), "=r"(a[mi][1]), "=r"(a[mi][2]), "=r"(a[mi][3])
                             : "r"(addr));
            }
            #pragma unroll
            for (int ng = 0; ng < 4; ng++) {
                int row = kk + (lane & 15);
                int col = wn + ng * 16 + (lane >> 4) * 8;
                uint32_t addr = (uint32_t)__cvta_generic_to_shared(&Bs[buf][row][col]);
                asm volatile("ldmatrix.sync.aligned.m8n8.x4.trans.shared.b16 {%0,%1,%2,%3},[%4];\n"
                             : "=r"(b[ng][0]), "=r"(b[ng][1]), "=r"(b[ng][2]), "=r"(b[ng][3])
                             : "r"(addr));
            }
            #pragma unroll
            for (int mi = 0; mi < 2; mi++)
                #pragma unroll
                for (int ni = 0; ni < 8; ni++) {
                    uint32_t b0 = b[ni >> 1][(ni & 1) * 2 + 0];
                    uint32_t b1 = b[ni >> 1][(ni & 1) * 2 + 1];
                    MMA16816(acc[mi][ni], a[mi][0], a[mi][1], a[mi][2], a[mi][3], b0, b1);
                }
        }
        __syncthreads();
    }

    #pragma unroll
    for (int mi = 0; mi < 2; mi++) {
        #pragma unroll
        for (int r = 0; r < 2; r++) {
            int gm = bm + wm + mi * 16 + (lane >> 2) + r * 8;
            if (gm >= M) continue;
            float cs = 0.0f;
            if constexpr (EPI == 2) cs = g_Ct[gm];
            #pragma unroll
            for (int ni = 0; ni < 8; ni++) {
                #pragma unroll
                for (int cc = 0; cc < 2; cc++) {
                    int gn = bn + wn + ni * 8 + (lane & 3) * 2 + cc;
                    if (gn >= H) continue;
                    float v = acc[mi][ni][r * 2 + cc];
                    if (bias) v += bias[gn];
                    if constexpr (EPI == 1) v = sspf(v);
                    if constexpr (EPI == 2) v *= cs;
                    if constexpr (EPI == 3) v += g_h[(size_t)gm * H + gn];
                    if constexpr (CF32 != B_NONE) Cf[(size_t)gm * H + gn] = v;
                    if constexpr (CSPL != B_NONE) {
                        __nv_bfloat16 hi, lo; split2(v, hi, lo);
                        size_t base = (size_t)gm * KP;
                        Cs[base + gn]         = hi;
                        Cs[base + H + gn]     = lo;
                        Cs[base + 2 * H + gn] = hi;
                    }
                }
            }
        }
    }
}

// ---------------- CFConv scatter: vectorized lerp + red.v4 ----------------
// agg[dst] += Y[src] * lerp(Wtab[i0], Wtab[i0+1], f), 4 channels per thread
__global__ void scatter_kernel(const int* __restrict__ ei) {
    int idx = blockIdx.x * blockDim.x + threadIdx.x;
    const int total = N_EDGES * H4;
    if (idx >= total) return;
    int e = idx / H4;
    int c4 = idx - e * H4;
    int s  = __ldg(&ei[e]);
    int d  = __ldg(&ei[N_EDGES + e]);
    int i0 = __ldg(&g_ei0[e]);
    float f = __ldg(&g_ef[e]);
    const float4 y  = *(const float4*)(g_Y    + (size_t)s * H        + c4 * 4);
    const float4 w0 = *(const float4*)(g_Wtab + (size_t)i0 * H       + c4 * 4);
    const float4 w1 = *(const float4*)(g_Wtab + (size_t)(i0 + 1) * H + c4 * 4);
    float v0 = y.x * fmaf(f, w1.x - w0.x, w0.x);
    float v1 = y.y * fmaf(f, w1.y - w0.y, w0.y);
    float v2 = y.z * fmaf(f, w1.z - w0.z, w0.z);
    float v3 = y.w * fmaf(f, w1.w - w0.w, w0.w);
    float* dst = g_agg + (size_t)d * H + c4 * 4;
    asm volatile("red.global.v4.f32.add [%0], {%1,%2,%3,%4};"
                 :: "l"(dst), "f"(v0), "f"(v1), "f"(v2), "f"(v3) : "memory");
}

// ---------------- pooling ----------------
__global__ void count_kernel(const int* __restrict__ batch) {
    int i = blockIdx.x * blockDim.x + threadIdx.x;
    if (i < N_ATOMS) atomicAdd(&g_cnt[batch[i]], 1.0f);
}
__global__ void pool_sum_kernel(const int* __restrict__ batch) {
    int idx = blockIdx.x * blockDim.x + threadIdx.x;
    const int total = N_ATOMS * H4;
    if (idx >= total) return;
    int i = idx / H4;
    int c4 = idx - i * H4;
    const float4 v = *(const float4*)(g_h + (size_t)i * H + c4 * 4);
    float* dst = g_pooled + (size_t)__ldg(&batch[i]) * H + c4 * 4;
    asm volatile("red.global.v4.f32.add [%0], {%1,%2,%3,%4};"
                 :: "l"(dst), "f"(v.x), "f"(v.y), "f"(v.z), "f"(v.w) : "memory");
}
__global__ void pool_div_kernel() {
    int idx = blockIdx.x * blockDim.x + threadIdx.x;
    if (idx < N_BATCH * H) g_pooled[idx] /= fmaxf(g_cnt[idx / H], 1.0f);
}

// ---------------- host side: only kernel launches ----------------
extern "C" void kernel_launch(void* const* d_in, const int* in_sizes, int n_in,
                              void* d_out, int out_size) {
    const int*   z         = (const int*)  d_in[0];
    const float* pos       = (const float*)d_in[1];
    const int*   batch     = (const int*)  d_in[2];
    const int*   ei        = (const int*)  d_in[3];
    const float* emb       = (const float*)d_in[4];
    const float* mlp_w1    = (const float*)d_in[5];
    const float* mlp_b1    = (const float*)d_in[6];
    const float* mlp_w2    = (const float*)d_in[7];
    const float* mlp_b2    = (const float*)d_in[8];
    const float* lin1_w    = (const float*)d_in[9];
    const float* lin2_w    = (const float*)d_in[10];
    const float* lin2_b    = (const float*)d_in[11];
    const float* int_lin_w = (const float*)d_in[12];
    const float* int_lin_b = (const float*)d_in[13];
    const float* pool_w    = (const float*)d_in[14];
    const float* pool_b    = (const float*)d_in[15];
    float* out = (float*)d_out;

    edge_geom_kernel<<<(N_EDGES + 255) / 256, 256>>>(pos, ei);
    rbf_table_kernel<<<(S_TAB + 255) / 256, 256>>>();
    embed_kernel<<<2048, 256>>>(z, emb);

    const dim3 gridT(5, S_TAB / GBM);                 // 5 x 16  (table GEMMs)
    const dim3 gridN(5, (N_ATOMS + GBM - 1) / GBM);   // 5 x 79
    const dim3 gridB(5, 1);
    const int SW_BLK1 = (G * H + 255) / 256;
    const int SW4_BLK = (4 * H * H + 255) / 256;
    const int SA_BLK  = (N_ATOMS * H + 255) / 256;
    const int SC_BLK  = (N_EDGES * H4 + 255) / 256;
    const int Z_BLK   = (N_ATOMS * H4 + 255) / 256;
    const int PS_BLK  = (N_ATOMS * H4 + 255) / 256;

    for (int k = 0; k < L; k++) {
        const float* w1  = mlp_w1    + (size_t)k * G * H;
        const float* b1  = mlp_b1    + (size_t)k * H;
        const float* w2  = mlp_w2    + (size_t)k * H * H;
        const float* b2  = mlp_b2    + (size_t)k * H;
        const float* l1w = lin1_w    + (size_t)k * H * H;
        const float* l2w = lin2_w    + (size_t)k * H * H;
        const float* l2b = lin2_b    + (size_t)k * H;
        const float* ilw = int_lin_w + (size_t)k * H * H;
        const float* ilb = int_lin_b + (size_t)k * H;

        split_w_kernel<B_W1S><<<SW_BLK1, 256>>>(w1, G);
        split_w4_kernel<<<SW4_BLK, 256>>>(w2, l1w, l2w, ilw);

        // T1 table = split(ssp(rbf_tab @ w1 + b1))        [S_TAB, H]
        hgemm_kernel<B_RBFS, B_W1S, B_NONE, B_T1S, 1>
            <<<gridT, 256>>>(b1, nullptr, S_TAB, KPG);
        // W table = (T1_tab @ w2 + b2) * C(d_tab)          [S_TAB, H] fp32
        hgemm_kernel<B_T1S, B_W2S, B_WTAB, B_NONE, 2>
            <<<gridT, 256>>>(b2, nullptr, S_TAB, KP);
        // Y = h @ lin1_w
        hgemm_kernel<B_HS, B_L1WS, B_Y, B_NONE, 0>
            <<<gridN, 256>>>(nullptr, nullptr, N_ATOMS, KP);
        // agg = scatter_add(Y[src] * lerp(Wtab, d_e), dst)
        zero_agg_kernel<<<Z_BLK, 256>>>();
        scatter_kernel<<<SC_BLK, 256>>>(ei);
        split_act_kernel<B_AGG, B_AGGS><<<SA_BLK, 256>>>(N_ATOMS);
        // x1s = split(ssp(agg @ lin2_w + lin2_b))
        hgemm_kernel<B_AGGS, B_L2WS, B_NONE, B_X1S, 1>
            <<<gridN, 256>>>(l2b, nullptr, N_ATOMS, KP);
        // h = h + (x1 @ int_lin_w + int_lin_b); also refresh hs
        hgemm_kernel<B_X1S, B_ILWS, B_H, B_HS, 3>
            <<<gridN, 256>>>(ilb, nullptr, N_ATOMS, KP);
    }

    zero_pool_kernel<<<(N_BATCH * H4 + 255) / 256, 256>>>();
    count_kernel<<<(N_ATOMS + 255) / 256, 256>>>(batch);
    pool_sum_kernel<<<PS_BLK, 256>>>(batch);
    pool_div_kernel<<<(N_BATCH * H + 255) / 256, 256>>>();
    split_act_kernel<B_POOLED, B_POOLS><<<(N_BATCH * H + 255) / 256, 256>>>(N_BATCH);
    split_w_kernel<B_PWS><<<(H * H + 255) / 256, 256>>>(pool_w, H);
    hgemm_kernel<B_POOLS, B_PWS, B_PARAM, B_NONE, 0>
        <<<gridB, 256>>>(pool_b, out, N_BATCH, KP);
}

// round 9
// speedup vs baseline: 5.3123x; 1.0916x over previous
#include <cuda_runtime.h>
#include <cuda_bf16.h>
#include <math.h>
#include <stdint.h>

// ---------------- problem constants ----------------
constexpr int N_ATOMS = 10000;
constexpr int N_EDGES = 64000;
constexpr int N_BATCH = 128;
constexpr int H = 600;
constexpr int H4 = H / 4;          // 150 float4 per row
constexpr int G = 50;
constexpr int L = 6;
constexpr float CUTOFF = 10.0f;
constexpr float LN2 = 0.69314718055994530942f;

constexpr int KP  = 1824;   // padded 3*H (multiple of 32)
constexpr int KPG = 160;    // padded 3*G (multiple of 32)
constexpr int S_TAB = 2048; // distance table rows
constexpr float DMAX = 8.66035f; // sqrt(3)*5 + margin

// ---------------- scratch (device globals, zero-initialized) ----------------
__device__ __nv_bfloat16 g_rbf_s[(size_t)S_TAB * KPG];    // split rbf TABLE
__device__ float         g_Ct[S_TAB];                     // cutoff at table pts
__device__ int           g_ei0[N_EDGES];                  // lerp base index
__device__ float         g_ef[N_EDGES];                   // lerp fraction
__device__ float         g_h[N_ATOMS * H];
__device__ __nv_bfloat16 g_hs[(size_t)N_ATOMS * KP];
__device__ __nv_bfloat16 g_T1s[(size_t)S_TAB * KP];       // split T1 TABLE
__device__ float         g_Wtab[(size_t)S_TAB * H];       // fp32 W TABLE (4.9MB)
__device__ float         g_Y[N_ATOMS * H];
__device__ float         g_agg[N_ATOMS * H];
__device__ __nv_bfloat16 g_aggs[(size_t)N_ATOMS * KP];
__device__ __nv_bfloat16 g_x1s[(size_t)N_ATOMS * KP];
__device__ float         g_pooled[N_BATCH * H];
__device__ __nv_bfloat16 g_pooled_s[(size_t)N_BATCH * KP];
__device__ float         g_cnt[N_BATCH];
// split weights for ALL layers (written once per launch, before the loop)
__device__ __nv_bfloat16 g_w1s[(size_t)L * KPG * H];
__device__ __nv_bfloat16 g_w2s[(size_t)L * KP * H];
__device__ __nv_bfloat16 g_l1ws[(size_t)L * KP * H];
__device__ __nv_bfloat16 g_l2ws[(size_t)L * KP * H];
__device__ __nv_bfloat16 g_ilws[(size_t)L * KP * H];
__device__ __nv_bfloat16 g_pws[(size_t)KP * H];

// ---------------- compile-time buffer picker ----------------
enum BufId { B_NONE = -1,
             B_RBFS = 0, B_T1S, B_HS, B_AGGS, B_X1S, B_POOLS,
             B_W1S, B_W2S, B_L1WS, B_L2WS, B_ILWS, B_PWS,
             B_WTAB, B_Y, B_H, B_AGG, B_POOLED, B_PARAM };

template <int B>
__device__ __forceinline__ __nv_bfloat16* bbuf() {
    if constexpr (B == B_RBFS)       return g_rbf_s;
    else if constexpr (B == B_T1S)   return g_T1s;
    else if constexpr (B == B_HS)    return g_hs;
    else if constexpr (B == B_AGGS)  return g_aggs;
    else if constexpr (B == B_X1S)   return g_x1s;
    else if constexpr (B == B_POOLS) return g_pooled_s;
    else if constexpr (B == B_W1S)   return g_w1s;
    else if constexpr (B == B_W2S)   return g_w2s;
    else if constexpr (B == B_L1WS)  return g_l1ws;
    else if constexpr (B == B_L2WS)  return g_l2ws;
    else if constexpr (B == B_ILWS)  return g_ilws;
    else return g_pws;
}
template <int B>
__device__ __forceinline__ float* fbuf(float* p) {
    if constexpr (B == B_WTAB)        return g_Wtab;
    else if constexpr (B == B_Y)      return g_Y;
    else if constexpr (B == B_H)      return g_h;
    else if constexpr (B == B_AGG)    return g_agg;
    else if constexpr (B == B_POOLED) return g_pooled;
    else return p;
}

// ---------------- helpers ----------------
__device__ __forceinline__ float sspf(float x) {
    return fmaxf(x, 0.0f) + log1pf(expf(-fabsf(x))) - LN2;
}
__device__ __forceinline__ void split2(float v, __nv_bfloat16& hi, __nv_bfloat16& lo) {
    hi = __float2bfloat16(v);
    lo = __float2bfloat16(v - __bfloat162float(hi));
}

// ---------------- edge geometry: per-edge lerp coords only ----------------
__global__ void edge_geom_kernel(const float* __restrict__ pos,
                                 const int* __restrict__ ei) {
    int e = blockIdx.x * blockDim.x + threadIdx.x;
    if (e >= N_EDGES) return;
    int s = ei[e];
    int d = ei[N_EDGES + e];
    float dx = pos[s * 3 + 0] - pos[d * 3 + 0];
    float dy = pos[s * 3 + 1] - pos[d * 3 + 1];
    float dz = pos[s * 3 + 2] - pos[d * 3 + 2];
    float dist = sqrtf(dx * dx + dy * dy + dz * dz + 1e-12f);
    float x = dist * ((float)(S_TAB - 1) / DMAX);
    int i0 = (int)x;
    if (i0 > S_TAB - 2) i0 = S_TAB - 2;
    g_ei0[e] = i0;
    g_ef[e] = x - (float)i0;
}

// ---------------- rbf table: split rbf at table points ----------------
__global__ void rbf_table_kernel() {
    int i = blockIdx.x * blockDim.x + threadIdx.x;
    if (i >= S_TAB) return;
    float dist = (float)i * (DMAX / (float)(S_TAB - 1));
    g_Ct[i] = 0.5f * (cosf(dist * (3.14159265358979323846f / CUTOFF)) + 1.0f);
    const float step = CUTOFF / (float)(G - 1);
    const float coeff = -0.5f / (step * step);
    size_t base = (size_t)i * KPG;
    #pragma unroll
    for (int g = 0; g < G; g++) {
        float t = dist - step * (float)g;
        float v = expf(coeff * t * t);
        __nv_bfloat16 hi, lo; split2(v, hi, lo);
        g_rbf_s[base + g]         = hi;
        g_rbf_s[base + G + g]     = lo;
        g_rbf_s[base + 2 * G + g] = hi;
    }
}

// ---------------- embedding gather (fp32 + split) ----------------
__global__ void embed_kernel(const int* __restrict__ z,
                             const float* __restrict__ emb) {
    int idx = blockIdx.x * blockDim.x + threadIdx.x;
    const int total = N_ATOMS * H;
    for (; idx < total; idx += gridDim.x * blockDim.x) {
        int i = idx / H;
        int c = idx - i * H;
        float v = emb[z[i] * H + c];
        g_h[idx] = v;
        __nv_bfloat16 hi, lo; split2(v, hi, lo);
        size_t base = (size_t)i * KP;
        g_hs[base + c]         = hi;
        g_hs[base + H + c]     = lo;
        g_hs[base + 2 * H + c] = hi;
    }
}

// ---------------- split ALL H x H layer weights (once per launch) ----------
__global__ void split_w_all_kernel(const float* __restrict__ w2,
                                   const float* __restrict__ l1w,
                                   const float* __restrict__ l2w,
                                   const float* __restrict__ ilw) {
    long long idx = (long long)blockIdx.x * blockDim.x + threadIdx.x;
    const int per = H * H;
    const long long total = (long long)L * 4 * per;
    if (idx >= total) return;
    int t = (int)(idx / per);          // 0 .. 4L-1
    int j = (int)(idx - (long long)t * per);
    int layer = t >> 2, which = t & 3;
    const float* src = ((which == 0) ? w2 : (which == 1) ? l1w
                      : (which == 2) ? l2w : ilw) + (size_t)layer * per;
    __nv_bfloat16* dst = ((which == 0) ? g_w2s : (which == 1) ? g_l1ws
                        : (which == 2) ? g_l2ws : g_ilws) + (size_t)layer * KP * H;
    int r = j / H, n = j - r * H;
    __nv_bfloat16 hi, lo; split2(src[j], hi, lo);
    dst[(size_t)r * H + n]           = hi;
    dst[(size_t)(H + r) * H + n]     = hi;
    dst[(size_t)(2 * H + r) * H + n] = lo;
}

// split all L mlp_w1 [G,H] + pool_w [H,H]
__global__ void split_w1_pool_kernel(const float* __restrict__ w1,
                                     const float* __restrict__ pw) {
    int idx = blockIdx.x * blockDim.x + threadIdx.x;
    const int tot1 = L * G * H;
    if (idx < tot1) {
        int layer = idx / (G * H);
        int j = idx - layer * (G * H);
        int r = j / H, n = j - r * H;
        __nv_bfloat16 hi, lo; split2(w1[idx], hi, lo);
        __nv_bfloat16* dst = g_w1s + (size_t)layer * KPG * H;
        dst[(size_t)r * H + n]           = hi;
        dst[(size_t)(G + r) * H + n]     = hi;
        dst[(size_t)(2 * G + r) * H + n] = lo;
    }
    int idx2 = idx - tot1;
    if (idx2 >= 0 && idx2 < H * H) {
        int r = idx2 / H, n = idx2 - r * H;
        __nv_bfloat16 hi, lo; split2(pw[idx2], hi, lo);
        g_pws[(size_t)r * H + n]           = hi;
        g_pws[(size_t)(H + r) * H + n]     = hi;
        g_pws[(size_t)(2 * H + r) * H + n] = lo;
    }
}

// ---------------- activation split: X[M,600] fp32 -> [hi|lo|hi] ----------------
template <int SRCF, int DSTB>
__global__ void split_act_kernel(int M) {
    const float* src = fbuf<SRCF>(nullptr);
    __nv_bfloat16* dst = bbuf<DSTB>();
    int idx = blockIdx.x * blockDim.x + threadIdx.x;
    int total = M * H;
    if (idx >= total) return;
    int m = idx / H, k = idx - m * H;
    __nv_bfloat16 hi, lo; split2(src[idx], hi, lo);
    size_t base = (size_t)m * KP;
    dst[base + k]         = hi;
    dst[base + H + k]     = lo;
    dst[base + 2 * H + k] = hi;
}

// ---------------- zero fills (vectorized) ----------------
__global__ void zero_agg_kernel() {
    int idx = blockIdx.x * blockDim.x + threadIdx.x;
    const int total = N_ATOMS * H4;
    if (idx < total) ((float4*)g_agg)[idx] = make_float4(0.f, 0.f, 0.f, 0.f);
}
__global__ void zero_pool_kernel() {
    int idx = blockIdx.x * blockDim.x + threadIdx.x;
    if (idx < N_BATCH * H4)
        ((float4*)g_pooled)[idx] = make_float4(0.f, 0.f, 0.f, 0.f);
    if (idx < N_BATCH) g_cnt[idx] = 0.0f;
}

// ---------------- HMMA GEMM: C = epi(A_split @ B_split + bias) ----------------
// 3-stage cp.async pipeline, dynamic smem.
constexpr int GBM = 128, GBN = 128, GBK = 32;
constexpr int APAD = 8, BPAD = 8;
constexpr int AST = GBK + APAD;                         // 40 elems
constexpr int BST = GBN + BPAD;                         // 136 elems
constexpr uint32_t A_BYTES = GBM * AST * 2;             // 10240
constexpr uint32_t B_BYTES = GBK * BST * 2;             // 8704
constexpr uint32_t STG_BYTES = A_BYTES + B_BYTES;       // 18944
constexpr int NSTAGE = 3;
constexpr uint32_t SMEM_SZ = NSTAGE * STG_BYTES;        // 56832

#define MMA16816(ac, A0, A1, A2, A3, B0, B1)                              \
    asm volatile(                                                         \
        "mma.sync.aligned.m16n8k16.row.col.f32.bf16.bf16.f32 "            \
        "{%0,%1,%2,%3},{%4,%5,%6,%7},{%8,%9},{%0,%1,%2,%3};\n"            \
        : "+f"(ac[0]), "+f"(ac[1]), "+f"(ac[2]), "+f"(ac[3])              \
        : "r"(A0), "r"(A1), "r"(A2), "r"(A3), "r"(B0), "r"(B1))

template <int ABUF, int BBUF, int CF32, int CSPL, int EPI>
__global__ __launch_bounds__(256, 2)
void hgemm_kernel(const float* __restrict__ bias, float* out_param,
                  size_t boff, int M, int KPa) {
    const __nv_bfloat16* __restrict__ A  = bbuf<ABUF>();
    const __nv_bfloat16* __restrict__ Bw = bbuf<BBUF>() + boff;
    float* Cf = nullptr;
    if constexpr (CF32 != B_NONE) Cf = fbuf<CF32>(out_param);
    __nv_bfloat16* Cs = nullptr;
    if constexpr (CSPL != B_NONE) Cs = bbuf<CSPL>();

    extern __shared__ char dsm[];
    uint32_t sb;
    asm("{ .reg .u64 t; cvta.to.shared.u64 t, %1; cvt.u32.u64 %0, t; }"
        : "=r"(sb) : "l"(dsm));

    const int tid = threadIdx.x;
    const int lane = tid & 31, wid = tid >> 5;
    const int wm = (wid >> 1) * 32;
    const int wn = (wid & 1) * 64;
    const int bm = blockIdx.y * GBM, bn = blockIdx.x * GBN;

    float acc[2][8][4];
    #pragma unroll
    for (int mi = 0; mi < 2; mi++)
        #pragma unroll
        for (int ni = 0; ni < 8; ni++)
            #pragma unroll
            for (int c = 0; c < 4; c++) acc[mi][ni][c] = 0.0f;

    const int KT = KPa / GBK;

    auto load_tiles = [&](int kt, int st) {
        int k0 = kt * GBK;
        uint32_t abase = sb + st * STG_BYTES;
        uint32_t bbase = abase + A_BYTES;
        #pragma unroll
        for (int c0 = 0; c0 < 2; c0++) {
            int c = tid + c0 * 256;
            int m = c >> 2, kc = (c & 3) * 8;
            const __nv_bfloat16* src = A + (size_t)(bm + m) * KPa + k0 + kc;
            uint32_t dst = abase + (m * AST + kc) * 2;
            int sz = (bm + m < M) ? 16 : 0;
            asm volatile("cp.async.cg.shared.global [%0],[%1],16,%2;\n"
                         :: "r"(dst), "l"(src), "r"(sz));
        }
        #pragma unroll
        for (int c0 = 0; c0 < 2; c0++) {
            int c = tid + c0 * 256;
            int k = c >> 4, nc = (c & 15) * 8;
            const __nv_bfloat16* src = Bw + (size_t)(k0 + k) * H + bn + nc;
            uint32_t dst = bbase + (k * BST + nc) * 2;
            int sz = (bn + nc < H) ? 16 : 0;
            asm volatile("cp.async.cg.shared.global [%0],[%1],16,%2;\n"
                         :: "r"(dst), "l"(src), "r"(sz));
        }
        asm volatile("cp.async.commit_group;\n");
    };

    int npre = (KT < NSTAGE) ? KT : NSTAGE;
    for (int s = 0; s < npre; s++) load_tiles(s, s);

    for (int kt = 0; kt < KT; kt++) {
        int remaining = KT - 1 - kt;
        if (remaining >= 2)      asm volatile("cp.async.wait_group 2;\n");
        else if (remaining == 1) asm volatile("cp.async.wait_group 1;\n");
        else                     asm volatile("cp.async.wait_group 0;\n");
        __syncthreads();

        int st = kt % NSTAGE;
        uint32_t abase = sb + st * STG_BYTES;
        uint32_t bbase = abase + A_BYTES;

        #pragma unroll
        for (int ks = 0; ks < 2; ks++) {
            const int kk = ks * 16;
            uint32_t a[2][4], b[4][4];
            #pragma unroll
            for (int mi = 0; mi < 2; mi++) {
                int row = wm + mi * 16 + (lane & 15);
                int col = kk + (lane >> 4) * 8;
                uint32_t addr = abase + (row * AST + col) * 2;
                asm volatile("ldmatrix.sync.aligned.m8n8.x4.shared.b16 {%0,%1,%2,%3},[%4];\n"
                             : "=r"(a[mi][0]), "=r"(a[mi][1]), "=r"(a[mi][2]), "=r"(a[mi][3])
                             : "r"(addr));
            }
            #pragma unroll
            for (int ng = 0; ng < 4; ng++) {
                int row = kk + (lane & 15);
                int col = wn + ng * 16 + (lane >> 4) * 8;
                uint32_t addr = bbase + (row * BST + col) * 2;
                asm volatile("ldmatrix.sync.aligned.m8n8.x4.trans.shared.b16 {%0,%1,%2,%3},[%4];\n"
                             : "=r"(b[ng][0]), "=r"(b[ng][1]), "=r"(b[ng][2]), "=r"(b[ng][3])
                             : "r"(addr));
            }
            #pragma unroll
            for (int mi = 0; mi < 2; mi++)
                #pragma unroll
                for (int ni = 0; ni < 8; ni++) {
                    uint32_t b0 = b[ni >> 1][(ni & 1) * 2 + 0];
                    uint32_t b1 = b[ni >> 1][(ni & 1) * 2 + 1];
                    MMA16816(acc[mi][ni], a[mi][0], a[mi][1], a[mi][2], a[mi][3], b0, b1);
                }
        }
        __syncthreads();
        if (kt + NSTAGE < KT) load_tiles(kt + NSTAGE, st);
    }

    #pragma unroll
    for (int mi = 0; mi < 2; mi++) {
        #pragma unroll
        for (int r = 0; r < 2; r++) {
            int gm = bm + wm + mi * 16 + (lane >> 2) + r * 8;
            if (gm >= M) continue;
            float cs = 0.0f;
            if constexpr (EPI == 2) cs = g_Ct[gm];
            #pragma unroll
            for (int ni = 0; ni < 8; ni++) {
                #pragma unroll
                for (int cc = 0; cc < 2; cc++) {
                    int gn = bn + wn + ni * 8 + (lane & 3) * 2 + cc;
                    if (gn >= H) continue;
                    float v = acc[mi][ni][r * 2 + cc];
                    if (bias) v += bias[gn];
                    if constexpr (EPI == 1) v = sspf(v);
                    if constexpr (EPI == 2) v *= cs;
                    if constexpr (EPI == 3) v += g_h[(size_t)gm * H + gn];
                    if constexpr (CF32 != B_NONE) Cf[(size_t)gm * H + gn] = v;
                    if constexpr (CSPL != B_NONE) {
                        __nv_bfloat16 hi, lo; split2(v, hi, lo);
                        size_t base = (size_t)gm * KP;
                        Cs[base + gn]         = hi;
                        Cs[base + H + gn]     = lo;
                        Cs[base + 2 * H + gn] = hi;
                    }
                }
            }
        }
    }
}

// ---------------- CFConv scatter: vectorized lerp + red.v4 ----------------
__global__ void scatter_kernel(const int* __restrict__ ei) {
    int idx = blockIdx.x * blockDim.x + threadIdx.x;
    const int total = N_EDGES * H4;
    if (idx >= total) return;
    int e = idx / H4;
    int c4 = idx - e * H4;
    int s  = __ldg(&ei[e]);
    int d  = __ldg(&ei[N_EDGES + e]);
    int i0 = __ldg(&g_ei0[e]);
    float f = __ldg(&g_ef[e]);
    const float4 y  = *(const float4*)(g_Y    + (size_t)s * H        + c4 * 4);
    const float4 w0 = *(const float4*)(g_Wtab + (size_t)i0 * H       + c4 * 4);
    const float4 w1 = *(const float4*)(g_Wtab + (size_t)(i0 + 1) * H + c4 * 4);
    float v0 = y.x * fmaf(f, w1.x - w0.x, w0.x);
    float v1 = y.y * fmaf(f, w1.y - w0.y, w0.y);
    float v2 = y.z * fmaf(f, w1.z - w0.z, w0.z);
    float v3 = y.w * fmaf(f, w1.w - w0.w, w0.w);
    float* dst = g_agg + (size_t)d * H + c4 * 4;
    asm volatile("red.global.v4.f32.add [%0], {%1,%2,%3,%4};"
                 :: "l"(dst), "f"(v0), "f"(v1), "f"(v2), "f"(v3) : "memory");
}

// ---------------- pooling ----------------
__global__ void count_kernel(const int* __restrict__ batch) {
    int i = blockIdx.x * blockDim.x + threadIdx.x;
    if (i < N_ATOMS) atomicAdd(&g_cnt[batch[i]], 1.0f);
}
__global__ void pool_sum_kernel(const int* __restrict__ batch) {
    int idx = blockIdx.x * blockDim.x + threadIdx.x;
    const int total = N_ATOMS * H4;
    if (idx >= total) return;
    int i = idx / H4;
    int c4 = idx - i * H4;
    const float4 v = *(const float4*)(g_h + (size_t)i * H + c4 * 4);
    float* dst = g_pooled + (size_t)__ldg(&batch[i]) * H + c4 * 4;
    asm volatile("red.global.v4.f32.add [%0], {%1,%2,%3,%4};"
                 :: "l"(dst), "f"(v.x), "f"(v.y), "f"(v.z), "f"(v.w) : "memory");
}
__global__ void pool_div_kernel() {
    int idx = blockIdx.x * blockDim.x + threadIdx.x;
    if (idx < N_BATCH * H) g_pooled[idx] /= fmaxf(g_cnt[idx / H], 1.0f);
}

// ---------------- host side ----------------
extern "C" void kernel_launch(void* const* d_in, const int* in_sizes, int n_in,
                              void* d_out, int out_size) {
    const int*   z         = (const int*)  d_in[0];
    const float* pos       = (const float*)d_in[1];
    const int*   batch     = (const int*)  d_in[2];
    const int*   ei        = (const int*)  d_in[3];
    const float* emb       = (const float*)d_in[4];
    const float* mlp_w1    = (const float*)d_in[5];
    const float* mlp_b1    = (const float*)d_in[6];
    const float* mlp_w2    = (const float*)d_in[7];
    const float* mlp_b2    = (const float*)d_in[8];
    const float* lin1_w    = (const float*)d_in[9];
    const float* lin2_w    = (const float*)d_in[10];
    const float* lin2_b    = (const float*)d_in[11];
    const float* int_lin_w = (const float*)d_in[12];
    const float* int_lin_b = (const float*)d_in[13];
    const float* pool_w    = (const float*)d_in[14];
    const float* pool_b    = (const float*)d_in[15];
    float* out = (float*)d_out;

    // opt-in to 56.8KB dynamic smem for each GEMM instantiation
    cudaFuncSetAttribute(hgemm_kernel<B_RBFS, B_W1S, B_NONE, B_T1S, 1>,
                         cudaFuncAttributeMaxDynamicSharedMemorySize, (int)SMEM_SZ);
    cudaFuncSetAttribute(hgemm_kernel<B_T1S, B_W2S, B_WTAB, B_NONE, 2>,
                         cudaFuncAttributeMaxDynamicSharedMemorySize, (int)SMEM_SZ);
    cudaFuncSetAttribute(hgemm_kernel<B_HS, B_L1WS, B_Y, B_NONE, 0>,
                         cudaFuncAttributeMaxDynamicSharedMemorySize, (int)SMEM_SZ);
    cudaFuncSetAttribute(hgemm_kernel<B_AGGS, B_L2WS, B_NONE, B_X1S, 1>,
                         cudaFuncAttributeMaxDynamicSharedMemorySize, (int)SMEM_SZ);
    cudaFuncSetAttribute(hgemm_kernel<B_X1S, B_ILWS, B_H, B_HS, 3>,
                         cudaFuncAttributeMaxDynamicSharedMemorySize, (int)SMEM_SZ);
    cudaFuncSetAttribute(hgemm_kernel<B_POOLS, B_PWS, B_PARAM, B_NONE, 0>,
                         cudaFuncAttributeMaxDynamicSharedMemorySize, (int)SMEM_SZ);

    edge_geom_kernel<<<(N_EDGES + 255) / 256, 256>>>(pos, ei);
    rbf_table_kernel<<<(S_TAB + 255) / 256, 256>>>();
    embed_kernel<<<2048, 256>>>(z, emb);
    // all weight splits up front (independent of layer loop state)
    {
        long long tot = (long long)L * 4 * H * H;
        split_w_all_kernel<<<(unsigned)((tot + 255) / 256), 256>>>(
            mlp_w2, lin1_w, lin2_w, int_lin_w);
        int tot2 = L * G * H + H * H;
        split_w1_pool_kernel<<<(tot2 + 255) / 256, 256>>>(mlp_w1, pool_w);
    }

    const dim3 gridT(5, S_TAB / GBM);                 // 5 x 16
    const dim3 gridN(5, (N_ATOMS + GBM - 1) / GBM);   // 5 x 79
    const dim3 gridB(5, 1);
    const int SA_BLK  = (N_ATOMS * H + 255) / 256;
    const int SC_BLK  = (N_EDGES * H4 + 255) / 256;
    const int Z_BLK   = (N_ATOMS * H4 + 255) / 256;

    for (int k = 0; k < L; k++) {
        const float* b1  = mlp_b1    + (size_t)k * H;
        const float* b2  = mlp_b2    + (size_t)k * H;
        const float* l2b = lin2_b    + (size_t)k * H;
        const float* ilb = int_lin_b + (size_t)k * H;
        const size_t o1 = (size_t)k * KPG * H;
        const size_t oh = (size_t)k * KP * H;

        // T1 table = split(ssp(rbf_tab @ w1 + b1))        [S_TAB, H]
        hgemm_kernel<B_RBFS, B_W1S, B_NONE, B_T1S, 1>
            <<<gridT, 256, SMEM_SZ>>>(b1, nullptr, o1, S_TAB, KPG);
        // W table = (T1_tab @ w2 + b2) * C(d_tab)          [S_TAB, H] fp32
        hgemm_kernel<B_T1S, B_W2S, B_WTAB, B_NONE, 2>
            <<<gridT, 256, SMEM_SZ>>>(b2, nullptr, oh, S_TAB, KP);
        // Y = h @ lin1_w
        hgemm_kernel<B_HS, B_L1WS, B_Y, B_NONE, 0>
            <<<gridN, 256, SMEM_SZ>>>(nullptr, nullptr, oh, N_ATOMS, KP);
        // agg = scatter_add(Y[src] * lerp(Wtab, d_e), dst)
        zero_agg_kernel<<<Z_BLK, 256>>>();
        scatter_kernel<<<SC_BLK, 256>>>(ei);
        split_act_kernel<B_AGG, B_AGGS><<<SA_BLK, 256>>>(N_ATOMS);
        // x1s = split(ssp(agg @ lin2_w + lin2_b))
        hgemm_kernel<B_AGGS, B_L2WS, B_NONE, B_X1S, 1>
            <<<gridN, 256, SMEM_SZ>>>(l2b, nullptr, oh, N_ATOMS, KP);
        // h = h + (x1 @ int_lin_w + int_lin_b); also refresh hs
        hgemm_kernel<B_X1S, B_ILWS, B_H, B_HS, 3>
            <<<gridN, 256, SMEM_SZ>>>(ilb, nullptr, oh, N_ATOMS, KP);
    }

    zero_pool_kernel<<<(N_BATCH * H4 + 255) / 256, 256>>>();
    count_kernel<<<(N_ATOMS + 255) / 256, 256>>>(batch);
    pool_sum_kernel<<<(N_ATOMS * H4 + 255) / 256, 256>>>(batch);
    pool_div_kernel<<<(N_BATCH * H + 255) / 256, 256>>>();
    split_act_kernel<B_POOLED, B_POOLS><<<(N_BATCH * H + 255) / 256, 256>>>(N_BATCH);
    hgemm_kernel<B_POOLS, B_PWS, B_PARAM, B_NONE, 0>
        <<<gridB, 256, SMEM_SZ>>>(pool_b, out, 0, N_BATCH, KP);
}

// round 10
// speedup vs baseline: 6.0775x; 1.1440x over previous
#include <cuda_runtime.h>
#include <cuda_bf16.h>
#include <math.h>
#include <stdint.h>

// ---------------- problem constants ----------------
constexpr int N_ATOMS = 10000;
constexpr int N_EDGES = 64000;
constexpr int N_BATCH = 128;
constexpr int H = 600;
constexpr int H4 = H / 4;
constexpr int G = 50;
constexpr int L = 6;
constexpr float CUTOFF = 10.0f;
constexpr float LN2 = 0.69314718055994530942f;

constexpr int KP  = 1824;   // padded 3*H (multiple of 32)
constexpr int KPG = 160;    // padded 3*G (multiple of 32)
constexpr int S_TAB = 1024; // distance table rows
constexpr float DMAX = 8.66035f;

// ---------------- scratch (device globals, zero-initialized) ----------------
__device__ __nv_bfloat16 g_rbf_s[(size_t)S_TAB * KPG];
__device__ float         g_Ct[S_TAB];
__device__ int           g_ei0[N_EDGES];
__device__ float         g_ef[N_EDGES];
__device__ float         g_h[N_ATOMS * H];
__device__ __nv_bfloat16 g_hs[(size_t)N_ATOMS * KP];
__device__ __nv_bfloat16 g_T1s[2 * (size_t)S_TAB * KP];   // ping-pong T1 table
__device__ float         g_Wtab[(size_t)S_TAB * H];
__device__ float         g_Y[N_ATOMS * H];
__device__ float         g_agg[N_ATOMS * H];
__device__ __nv_bfloat16 g_aggs[(size_t)N_ATOMS * KP];
__device__ __nv_bfloat16 g_x1s[(size_t)N_ATOMS * KP];
__device__ float         g_pooled[N_BATCH * H];
__device__ __nv_bfloat16 g_pooled_s[(size_t)N_BATCH * KP];
__device__ float         g_cnt[N_BATCH];
// split weights for ALL layers (written once per launch, before the loop)
__device__ __nv_bfloat16 g_w1s[(size_t)L * KPG * H];
__device__ __nv_bfloat16 g_w2s[(size_t)L * KP * H];
__device__ __nv_bfloat16 g_l1ws[(size_t)L * KP * H];
__device__ __nv_bfloat16 g_l2ws[(size_t)L * KP * H];
__device__ __nv_bfloat16 g_ilws[(size_t)L * KP * H];
__device__ __nv_bfloat16 g_pws[(size_t)KP * H];

// ---------------- compile-time buffer picker ----------------
enum BufId { B_NONE = -1,
             B_RBFS = 0, B_T1S, B_HS, B_AGGS, B_X1S, B_POOLS,
             B_W1S, B_W2S, B_L1WS, B_L2WS, B_ILWS, B_PWS,
             B_WTAB, B_Y, B_H, B_AGG, B_POOLED, B_PARAM };

template <int B>
__device__ __forceinline__ __nv_bfloat16* bbuf() {
    if constexpr (B == B_RBFS)       return g_rbf_s;
    else if constexpr (B == B_T1S)   return g_T1s;
    else if constexpr (B == B_HS)    return g_hs;
    else if constexpr (B == B_AGGS)  return g_aggs;
    else if constexpr (B == B_X1S)   return g_x1s;
    else if constexpr (B == B_POOLS) return g_pooled_s;
    else if constexpr (B == B_W1S)   return g_w1s;
    else if constexpr (B == B_W2S)   return g_w2s;
    else if constexpr (B == B_L1WS)  return g_l1ws;
    else if constexpr (B == B_L2WS)  return g_l2ws;
    else if constexpr (B == B_ILWS)  return g_ilws;
    else return g_pws;
}
template <int B>
__device__ __forceinline__ float* fbuf(float* p) {
    if constexpr (B == B_WTAB)        return g_Wtab;
    else if constexpr (B == B_Y)      return g_Y;
    else if constexpr (B == B_H)      return g_h;
    else if constexpr (B == B_AGG)    return g_agg;
    else if constexpr (B == B_POOLED) return g_pooled;
    else return p;
}

// ---------------- helpers ----------------
__device__ __forceinline__ float sspf(float x) {
    return fmaxf(x, 0.0f) + log1pf(expf(-fabsf(x))) - LN2;
}
__device__ __forceinline__ void split2(float v, __nv_bfloat16& hi, __nv_bfloat16& lo) {
    hi = __float2bfloat16(v);
    lo = __float2bfloat16(v - __bfloat162float(hi));
}

// ---------------- edge geometry ----------------
__global__ void edge_geom_kernel(const float* __restrict__ pos,
                                 const int* __restrict__ ei) {
    int e = blockIdx.x * blockDim.x + threadIdx.x;
    if (e >= N_EDGES) return;
    int s = ei[e];
    int d = ei[N_EDGES + e];
    float dx = pos[s * 3 + 0] - pos[d * 3 + 0];
    float dy = pos[s * 3 + 1] - pos[d * 3 + 1];
    float dz = pos[s * 3 + 2] - pos[d * 3 + 2];
    float dist = sqrtf(dx * dx + dy * dy + dz * dz + 1e-12f);
    float x = dist * ((float)(S_TAB - 1) / DMAX);
    int i0 = (int)x;
    if (i0 > S_TAB - 2) i0 = S_TAB - 2;
    g_ei0[e] = i0;
    g_ef[e] = x - (float)i0;
}

// ---------------- rbf table ----------------
__global__ void rbf_table_kernel() {
    int i = blockIdx.x * blockDim.x + threadIdx.x;
    if (i >= S_TAB) return;
    float dist = (float)i * (DMAX / (float)(S_TAB - 1));
    g_Ct[i] = 0.5f * (cosf(dist * (3.14159265358979323846f / CUTOFF)) + 1.0f);
    const float step = CUTOFF / (float)(G - 1);
    const float coeff = -0.5f / (step * step);
    size_t base = (size_t)i * KPG;
    #pragma unroll
    for (int g = 0; g < G; g++) {
        float t = dist - step * (float)g;
        float v = expf(coeff * t * t);
        __nv_bfloat16 hi, lo; split2(v, hi, lo);
        g_rbf_s[base + g]         = hi;
        g_rbf_s[base + G + g]     = lo;
        g_rbf_s[base + 2 * G + g] = hi;
    }
}

// ---------------- embedding gather ----------------
__global__ void embed_kernel(const int* __restrict__ z,
                             const float* __restrict__ emb) {
    int idx = blockIdx.x * blockDim.x + threadIdx.x;
    const int total = N_ATOMS * H;
    for (; idx < total; idx += gridDim.x * blockDim.x) {
        int i = idx / H;
        int c = idx - i * H;
        float v = emb[z[i] * H + c];
        g_h[idx] = v;
        __nv_bfloat16 hi, lo; split2(v, hi, lo);
        size_t base = (size_t)i * KP;
        g_hs[base + c]         = hi;
        g_hs[base + H + c]     = lo;
        g_hs[base + 2 * H + c] = hi;
    }
}

// ---------------- split ALL H x H layer weights ----------------
__global__ void split_w_all_kernel(const float* __restrict__ w2,
                                   const float* __restrict__ l1w,
                                   const float* __restrict__ l2w,
                                   const float* __restrict__ ilw) {
    long long idx = (long long)blockIdx.x * blockDim.x + threadIdx.x;
    const int per = H * H;
    const long long total = (long long)L * 4 * per;
    if (idx >= total) return;
    int t = (int)(idx / per);
    int j = (int)(idx - (long long)t * per);
    int layer = t >> 2, which = t & 3;
    const float* src = ((which == 0) ? w2 : (which == 1) ? l1w
                      : (which == 2) ? l2w : ilw) + (size_t)layer * per;
    __nv_bfloat16* dst = ((which == 0) ? g_w2s : (which == 1) ? g_l1ws
                        : (which == 2) ? g_l2ws : g_ilws) + (size_t)layer * KP * H;
    int r = j / H, n = j - r * H;
    __nv_bfloat16 hi, lo; split2(src[j], hi, lo);
    dst[(size_t)r * H + n]           = hi;
    dst[(size_t)(H + r) * H + n]     = hi;
    dst[(size_t)(2 * H + r) * H + n] = lo;
}

__global__ void split_w1_pool_kernel(const float* __restrict__ w1,
                                     const float* __restrict__ pw) {
    int idx = blockIdx.x * blockDim.x + threadIdx.x;
    const int tot1 = L * G * H;
    if (idx < tot1) {
        int layer = idx / (G * H);
        int j = idx - layer * (G * H);
        int r = j / H, n = j - r * H;
        __nv_bfloat16 hi, lo; split2(w1[idx], hi, lo);
        __nv_bfloat16* dst = g_w1s + (size_t)layer * KPG * H;
        dst[(size_t)r * H + n]           = hi;
        dst[(size_t)(G + r) * H + n]     = hi;
        dst[(size_t)(2 * G + r) * H + n] = lo;
    }
    int idx2 = idx - tot1;
    if (idx2 >= 0 && idx2 < H * H) {
        int r = idx2 / H, n = idx2 - r * H;
        __nv_bfloat16 hi, lo; split2(pw[idx2], hi, lo);
        g_pws[(size_t)r * H + n]           = hi;
        g_pws[(size_t)(H + r) * H + n]     = hi;
        g_pws[(size_t)(2 * H + r) * H + n] = lo;
    }
}

// ---------------- activation split ----------------
template <int SRCF, int DSTB>
__global__ void split_act_kernel(int M) {
    const float* src = fbuf<SRCF>(nullptr);
    __nv_bfloat16* dst = bbuf<DSTB>();
    int idx = blockIdx.x * blockDim.x + threadIdx.x;
    int total = M * H;
    if (idx >= total) return;
    int m = idx / H, k = idx - m * H;
    __nv_bfloat16 hi, lo; split2(src[idx], hi, lo);
    size_t base = (size_t)m * KP;
    dst[base + k]         = hi;
    dst[base + H + k]     = lo;
    dst[base + 2 * H + k] = hi;
}

// ---------------- pooling small kernels ----------------
__global__ void zero_pool_kernel() {
    int idx = blockIdx.x * blockDim.x + threadIdx.x;
    if (idx < N_BATCH * H4)
        ((float4*)g_pooled)[idx] = make_float4(0.f, 0.f, 0.f, 0.f);
    if (idx < N_BATCH) g_cnt[idx] = 0.0f;
}
__global__ void count_kernel(const int* __restrict__ batch) {
    int i = blockIdx.x * blockDim.x + threadIdx.x;
    if (i < N_ATOMS) atomicAdd(&g_cnt[batch[i]], 1.0f);
}
__global__ void pool_sum_kernel(const int* __restrict__ batch) {
    int idx = blockIdx.x * blockDim.x + threadIdx.x;
    const int total = N_ATOMS * H4;
    if (idx >= total) return;
    int i = idx / H4;
    int c4 = idx - i * H4;
    const float4 v = *(const float4*)(g_h + (size_t)i * H + c4 * 4);
    float* dst = g_pooled + (size_t)__ldg(&batch[i]) * H + c4 * 4;
    asm volatile("red.global.v4.f32.add [%0], {%1,%2,%3,%4};"
                 :: "l"(dst), "f"(v.x), "f"(v.y), "f"(v.z), "f"(v.w) : "memory");
}
// divide by count AND write split in one pass
__global__ void pool_divsplit_kernel() {
    int idx = blockIdx.x * blockDim.x + threadIdx.x;
    if (idx >= N_BATCH * H) return;
    int b = idx / H, c = idx - b * H;
    float v = g_pooled[idx] / fmaxf(g_cnt[b], 1.0f);
    __nv_bfloat16 hi, lo; split2(v, hi, lo);
    size_t base = (size_t)b * KP;
    g_pooled_s[base + c]         = hi;
    g_pooled_s[base + H + c]     = lo;
    g_pooled_s[base + 2 * H + c] = hi;
}

// ---------------- HMMA GEMM body (3-stage cp.async pipeline) ----------------
constexpr int GBM = 128, GBN = 128, GBK = 32;
constexpr int APAD = 8, BPAD = 8;
constexpr int AST = GBK + APAD;
constexpr int BST = GBN + BPAD;
constexpr uint32_t A_BYTES = GBM * AST * 2;
constexpr uint32_t B_BYTES = GBK * BST * 2;
constexpr uint32_t STG_BYTES = A_BYTES + B_BYTES;
constexpr int NSTAGE = 3;
constexpr uint32_t SMEM_SZ = NSTAGE * STG_BYTES;        // 56832

#define MMA16816(ac, A0, A1, A2, A3, B0, B1)                              \
    asm volatile(                                                         \
        "mma.sync.aligned.m16n8k16.row.col.f32.bf16.bf16.f32 "            \
        "{%0,%1,%2,%3},{%4,%5,%6,%7},{%8,%9},{%0,%1,%2,%3};\n"            \
        : "+f"(ac[0]), "+f"(ac[1]), "+f"(ac[2]), "+f"(ac[3])              \
        : "r"(A0), "r"(A1), "r"(A2), "r"(A3), "r"(B0), "r"(B1))

// EPI: 0 = +bias, 1 = ssp(+bias), 2 = (+bias)*g_Ct[m], 3 = +bias + g_h[m,n]
// ZAGG: epilogue also zeroes g_agg[gm,gn]
template <int ABUF, int BBUF, int CF32, int CSPL, int EPI, bool ZAGG,
          int M_, int KPA_>
__device__ __forceinline__
void gemm_body(const float* __restrict__ bias, float* out_param,
               size_t aoff, size_t boff, size_t csoff, int by) {
    const __nv_bfloat16* __restrict__ A  = bbuf<ABUF>() + aoff;
    const __nv_bfloat16* __restrict__ Bw = bbuf<BBUF>() + boff;
    float* Cf = nullptr;
    if constexpr (CF32 != B_NONE) Cf = fbuf<CF32>(out_param);
    __nv_bfloat16* Cs = nullptr;
    if constexpr (CSPL != B_NONE) Cs = bbuf<CSPL>() + csoff;

    extern __shared__ char dsm[];
    uint32_t sb;
    asm("{ .reg .u64 t; cvta.to.shared.u64 t, %1; cvt.u32.u64 %0, t; }"
        : "=r"(sb) : "l"(dsm));

    const int tid = threadIdx.x;
    const int lane = tid & 31, wid = tid >> 5;
    const int wm = (wid >> 1) * 32;
    const int wn = (wid & 1) * 64;
    const int bm = by * GBM, bn = blockIdx.x * GBN;

    float acc[2][8][4];
    #pragma unroll
    for (int mi = 0; mi < 2; mi++)
        #pragma unroll
        for (int ni = 0; ni < 8; ni++)
            #pragma unroll
            for (int c = 0; c < 4; c++) acc[mi][ni][c] = 0.0f;

    constexpr int KT = KPA_ / GBK;

    auto load_tiles = [&](int kt, int st) {
        int k0 = kt * GBK;
        uint32_t abase = sb + st * STG_BYTES;
        uint32_t bbase = abase + A_BYTES;
        #pragma unroll
        for (int c0 = 0; c0 < 2; c0++) {
            int c = tid + c0 * 256;
            int m = c >> 2, kc = (c & 3) * 8;
            const __nv_bfloat16* src = A + (size_t)(bm + m) * KPA_ + k0 + kc;
            uint32_t dst = abase + (m * AST + kc) * 2;
            int sz = (bm + m < M_) ? 16 : 0;
            asm volatile("cp.async.cg.shared.global [%0],[%1],16,%2;\n"
                         :: "r"(dst), "l"(src), "r"(sz));
        }
        #pragma unroll
        for (int c0 = 0; c0 < 2; c0++) {
            int c = tid + c0 * 256;
            int k = c >> 4, nc = (c & 15) * 8;
            const __nv_bfloat16* src = Bw + (size_t)(k0 + k) * H + bn + nc;
            uint32_t dst = bbase + (k * BST + nc) * 2;
            int sz = (bn + nc < H) ? 16 : 0;
            asm volatile("cp.async.cg.shared.global [%0],[%1],16,%2;\n"
                         :: "r"(dst), "l"(src), "r"(sz));
        }
        asm volatile("cp.async.commit_group;\n");
    };

    constexpr int npre = (KT < NSTAGE) ? KT : NSTAGE;
    #pragma unroll
    for (int s = 0; s < npre; s++) load_tiles(s, s);

    #pragma unroll 1
    for (int kt = 0; kt < KT; kt++) {
        int remaining = KT - 1 - kt;
        if (remaining >= 2)      asm volatile("cp.async.wait_group 2;\n");
        else if (remaining == 1) asm volatile("cp.async.wait_group 1;\n");
        else                     asm volatile("cp.async.wait_group 0;\n");
        __syncthreads();

        int st = kt % NSTAGE;
        uint32_t abase = sb + st * STG_BYTES;
        uint32_t bbase = abase + A_BYTES;

        #pragma unroll
        for (int ks = 0; ks < 2; ks++) {
            const int kk = ks * 16;
            uint32_t a[2][4], b[4][4];
            #pragma unroll
            for (int mi = 0; mi < 2; mi++) {
                int row = wm + mi * 16 + (lane & 15);
                int col = kk + (lane >> 4) * 8;
                uint32_t addr = abase + (row * AST + col) * 2;
                asm volatile("ldmatrix.sync.aligned.m8n8.x4.shared.b16 {%0,%1,%2,%3},[%4];\n"
                             : "=r"(a[mi][0]), "=r"(a[mi][1]), "=r"(a[mi][2]), "=r"(a[mi][3])
                             : "r"(addr));
            }
            #pragma unroll
            for (int ng = 0; ng < 4; ng++) {
                int row = kk + (lane & 15);
                int col = wn + ng * 16 + (lane >> 4) * 8;
                uint32_t addr = bbase + (row * BST + col) * 2;
                asm volatile("ldmatrix.sync.aligned.m8n8.x4.trans.shared.b16 {%0,%1,%2,%3},[%4];\n"
                             : "=r"(b[ng][0]), "=r"(b[ng][1]), "=r"(b[ng][2]), "=r"(b[ng][3])
                             : "r"(addr));
            }
            #pragma unroll
            for (int mi = 0; mi < 2; mi++)
                #pragma unroll
                for (int ni = 0; ni < 8; ni++) {
                    uint32_t b0 = b[ni >> 1][(ni & 1) * 2 + 0];
                    uint32_t b1 = b[ni >> 1][(ni & 1) * 2 + 1];
                    MMA16816(acc[mi][ni], a[mi][0], a[mi][1], a[mi][2], a[mi][3], b0, b1);
                }
        }
        __syncthreads();
        if (kt + NSTAGE < KT) load_tiles(kt + NSTAGE, st);
    }

    #pragma unroll
    for (int mi = 0; mi < 2; mi++) {
        #pragma unroll
        for (int r = 0; r < 2; r++) {
            int gm = bm + wm + mi * 16 + (lane >> 2) + r * 8;
            if (gm >= M_) continue;
            float cs = 0.0f;
            if constexpr (EPI == 2) cs = g_Ct[gm];
            #pragma unroll
            for (int ni = 0; ni < 8; ni++) {
                #pragma unroll
                for (int cc = 0; cc < 2; cc++) {
                    int gn = bn + wn + ni * 8 + (lane & 3) * 2 + cc;
                    if (gn >= H) continue;
                    float v = acc[mi][ni][r * 2 + cc];
                    if (bias) v += bias[gn];
                    if constexpr (EPI == 1) v = sspf(v);
                    if constexpr (EPI == 2) v *= cs;
                    if constexpr (EPI == 3) v += g_h[(size_t)gm * H + gn];
                    if constexpr (CF32 != B_NONE) Cf[(size_t)gm * H + gn] = v;
                    if constexpr (ZAGG) g_agg[(size_t)gm * H + gn] = 0.0f;
                    if constexpr (CSPL != B_NONE) {
                        __nv_bfloat16 hi, lo; split2(v, hi, lo);
                        size_t base = (size_t)gm * KP;
                        Cs[base + gn]         = hi;
                        Cs[base + H + gn]     = lo;
                        Cs[base + 2 * H + gn] = hi;
                    }
                }
            }
        }
    }
}

// single-problem GEMM
template <int ABUF, int BBUF, int CF32, int CSPL, int EPI, bool ZAGG,
          int M_, int KPA_>
__global__ __launch_bounds__(256, 2)
void hgemm_kernel(const float* __restrict__ bias, float* out_param,
                  size_t aoff, size_t boff, size_t csoff) {
    gemm_body<ABUF, BBUF, CF32, CSPL, EPI, ZAGG, M_, KPA_>(
        bias, out_param, aoff, boff, csoff, blockIdx.y);
}

// fused launch: [ Y(k) + zero_agg | Wtab(k) | T1tab(k+1) ]
constexpr int NBY_Y = (N_ATOMS + GBM - 1) / GBM;   // 79
constexpr int NBY_T = S_TAB / GBM;                 // 8
__global__ __launch_bounds__(256, 2)
void hgemm_fused3(const float* __restrict__ b2, const float* __restrict__ b1n,
                  size_t offL1, size_t offW2, size_t offW1n,
                  size_t t1rd, size_t t1wr) {
    int by = blockIdx.y;
    if (by < NBY_Y) {
        // Y = h @ lin1_w ; also zero agg
        gemm_body<B_HS, B_L1WS, B_Y, B_NONE, 0, true, N_ATOMS, KP>(
            nullptr, nullptr, 0, offL1, 0, by);
    } else if (by < NBY_Y + NBY_T) {
        // Wtab = (T1tab @ w2 + b2) * Ct
        gemm_body<B_T1S, B_W2S, B_WTAB, B_NONE, 2, false, S_TAB, KP>(
            b2, nullptr, t1rd, offW2, 0, by - NBY_Y);
    } else {
        // T1tab(next) = split(ssp(rbf_tab @ w1_next + b1_next))
        gemm_body<B_RBFS, B_W1S, B_NONE, B_T1S, 1, false, S_TAB, KPG>(
            b1n, nullptr, 0, offW1n, t1wr, by - NBY_Y - NBY_T);
    }
}

// ---------------- CFConv scatter: vectorized lerp + red.v4 ----------------
__global__ void scatter_kernel(const int* __restrict__ ei) {
    int idx = blockIdx.x * blockDim.x + threadIdx.x;
    const int total = N_EDGES * H4;
    if (idx >= total) return;
    int e = idx / H4;
    int c4 = idx - e * H4;
    int s  = __ldg(&ei[e]);
    int d  = __ldg(&ei[N_EDGES + e]);
    int i0 = __ldg(&g_ei0[e]);
    float f = __ldg(&g_ef[e]);
    const float4 y  = *(const float4*)(g_Y    + (size_t)s * H        + c4 * 4);
    const float4 w0 = *(const float4*)(g_Wtab + (size_t)i0 * H       + c4 * 4);
    const float4 w1 = *(const float4*)(g_Wtab + (size_t)(i0 + 1) * H + c4 * 4);
    float v0 = y.x * fmaf(f, w1.x - w0.x, w0.x);
    float v1 = y.y * fmaf(f, w1.y - w0.y, w0.y);
    float v2 = y.z * fmaf(f, w1.z - w0.z, w0.z);
    float v3 = y.w * fmaf(f, w1.w - w0.w, w0.w);
    float* dst = g_agg + (size_t)d * H + c4 * 4;
    asm volatile("red.global.v4.f32.add [%0], {%1,%2,%3,%4};"
                 :: "l"(dst), "f"(v0), "f"(v1), "f"(v2), "f"(v3) : "memory");
}

// ---------------- host side ----------------
extern "C" void kernel_launch(void* const* d_in, const int* in_sizes, int n_in,
                              void* d_out, int out_size) {
    const int*   z         = (const int*)  d_in[0];
    const float* pos       = (const float*)d_in[1];
    const int*   batch     = (const int*)  d_in[2];
    const int*   ei        = (const int*)  d_in[3];
    const float* emb       = (const float*)d_in[4];
    const float* mlp_w1    = (const float*)d_in[5];
    const float* mlp_b1    = (const float*)d_in[6];
    const float* mlp_w2    = (const float*)d_in[7];
    const float* mlp_b2    = (const float*)d_in[8];
    const float* lin1_w    = (const float*)d_in[9];
    const float* lin2_w    = (const float*)d_in[10];
    const float* lin2_b    = (const float*)d_in[11];
    const float* int_lin_w = (const float*)d_in[12];
    const float* int_lin_b = (const float*)d_in[13];
    const float* pool_w    = (const float*)d_in[14];
    const float* pool_b    = (const float*)d_in[15];
    float* out = (float*)d_out;

    // opt-in to dynamic smem for every GEMM entry point
    cudaFuncSetAttribute(hgemm_kernel<B_RBFS, B_W1S, B_NONE, B_T1S, 1, false, S_TAB, KPG>,
                         cudaFuncAttributeMaxDynamicSharedMemorySize, (int)SMEM_SZ);
    cudaFuncSetAttribute(hgemm_fused3,
                         cudaFuncAttributeMaxDynamicSharedMemorySize, (int)SMEM_SZ);
    cudaFuncSetAttribute(hgemm_kernel<B_AGGS, B_L2WS, B_NONE, B_X1S, 1, false, N_ATOMS, KP>,
                         cudaFuncAttributeMaxDynamicSharedMemorySize, (int)SMEM_SZ);
    cudaFuncSetAttribute(hgemm_kernel<B_X1S, B_ILWS, B_H, B_HS, 3, false, N_ATOMS, KP>,
                         cudaFuncAttributeMaxDynamicSharedMemorySize, (int)SMEM_SZ);
    cudaFuncSetAttribute(hgemm_kernel<B_POOLS, B_PWS, B_PARAM, B_NONE, 0, false, N_BATCH, KP>,
                         cudaFuncAttributeMaxDynamicSharedMemorySize, (int)SMEM_SZ);

    edge_geom_kernel<<<(N_EDGES + 255) / 256, 256>>>(pos, ei);
    rbf_table_kernel<<<(S_TAB + 255) / 256, 256>>>();
    embed_kernel<<<2048, 256>>>(z, emb);
    {
        long long tot = (long long)L * 4 * H * H;
        split_w_all_kernel<<<(unsigned)((tot + 255) / 256), 256>>>(
            mlp_w2, lin1_w, lin2_w, int_lin_w);
        int tot2 = L * G * H + H * H;
        split_w1_pool_kernel<<<(tot2 + 255) / 256, 256>>>(mlp_w1, pool_w);
    }
    // prologue: T1tab(0) into ping-pong slot 0
    hgemm_kernel<B_RBFS, B_W1S, B_NONE, B_T1S, 1, false, S_TAB, KPG>
        <<<dim3(5, NBY_T), 256, SMEM_SZ>>>(mlp_b1, nullptr, 0, 0, 0);

    const dim3 gridN(5, NBY_Y);
    const dim3 gridB(5, 1);
    const int SA_BLK = (N_ATOMS * H + 255) / 256;
    const int SC_BLK = (N_EDGES * H4 + 255) / 256;
    const size_t T1SZ = (size_t)S_TAB * KP;

    for (int k = 0; k < L; k++) {
        const float* b2  = mlp_b2    + (size_t)k * H;
        const float* l2b = lin2_b    + (size_t)k * H;
        const float* ilb = int_lin_b + (size_t)k * H;
        const size_t oh  = (size_t)k * KP * H;
        const bool hasNext = (k + 1 < L);
        const float* b1n = hasNext ? (mlp_b1 + (size_t)(k + 1) * H) : nullptr;
        const size_t o1n = hasNext ? (size_t)(k + 1) * KPG * H : 0;
        const size_t t1rd = (size_t)(k & 1) * T1SZ;
        const size_t t1wr = (size_t)((k + 1) & 1) * T1SZ;

        // fused: Y(k)+zero_agg | Wtab(k) | T1tab(k+1)
        int gy = NBY_Y + NBY_T + (hasNext ? NBY_T : 0);
        hgemm_fused3<<<dim3(5, gy), 256, SMEM_SZ>>>(
            b2, b1n, oh, oh, o1n, t1rd, t1wr);
        // agg = scatter_add(Y[src] * lerp(Wtab, d_e), dst)
        scatter_kernel<<<SC_BLK, 256>>>(ei);
        split_act_kernel<B_AGG, B_AGGS><<<SA_BLK, 256>>>(N_ATOMS);
        // x1s = split(ssp(agg @ lin2_w + lin2_b))
        hgemm_kernel<B_AGGS, B_L2WS, B_NONE, B_X1S, 1, false, N_ATOMS, KP>
            <<<gridN, 256, SMEM_SZ>>>(l2b, nullptr, 0, oh, 0);
        // h = h + (x1 @ int_lin_w + int_lin_b); also refresh hs
        hgemm_kernel<B_X1S, B_ILWS, B_H, B_HS, 3, false, N_ATOMS, KP>
            <<<gridN, 256, SMEM_SZ>>>(ilb, nullptr, 0, oh, 0);
    }

    zero_pool_kernel<<<(N_BATCH * H4 + 255) / 256, 256>>>();
    count_kernel<<<(N_ATOMS + 255) / 256, 256>>>(batch);
    pool_sum_kernel<<<(N_ATOMS * H4 + 255) / 256, 256>>>(batch);
    pool_divsplit_kernel<<<(N_BATCH * H + 255) / 256, 256>>>();
    hgemm_kernel<B_POOLS, B_PWS, B_PARAM, B_NONE, 0, false, N_BATCH, KP>
        <<<gridB, 256, SMEM_SZ>>>(pool_b, out, 0, 0, 0);
}